// round 1
// baseline (speedup 1.0000x reference)
#include <cuda_runtime.h>
#include <cuda_bf16.h>
#include <math.h>

// Problem dims
#define NB 8
#define CC 512
#define SS 4096     // N = H*W tokens
#define HD 2048     // HID = 4*C
#define HH 64

// ---------------- scratch (device globals; no allocation allowed) ----------
__device__ float g_q  [(long long)NB*CC*SS];   // 64MB, (B, o, s) == (B, N, C) view
__device__ float g_k  [(long long)NB*CC*SS];
__device__ float g_v  [(long long)NB*CC*SS];
__device__ float g_sc [(long long)NB*SS*CC];   // shortcut = x transposed (B, N, C)
__device__ float g_enh[(long long)NB*SS*CC];
__device__ float g_t  [(long long)NB*SS*CC];
__device__ float g_a  [(long long)NB*SS*HD];   // 256MB
__device__ float g_ax [(long long)NB*SS*HD];   // 256MB
__device__ float g_kv [(long long)NB*CC*CC];
__device__ float g_ksum[NB*CC];
__device__ float g_z  [NB*SS];

// ---------------- helpers ---------------------------------------------------
__device__ __forceinline__ float blockReduceSum(float val) {
    __shared__ float sh[32];
    int lane = threadIdx.x & 31, wid = threadIdx.x >> 5;
    #pragma unroll
    for (int o = 16; o > 0; o >>= 1) val += __shfl_xor_sync(0xffffffff, val, o);
    if (lane == 0) sh[wid] = val;
    __syncthreads();
    float tot = 0.f;
    if (wid == 0) {
        tot = (lane < (int)(blockDim.x >> 5)) ? sh[lane] : 0.f;
        #pragma unroll
        for (int o = 16; o > 0; o >>= 1) tot += __shfl_xor_sync(0xffffffff, tot, o);
        if (lane == 0) sh[0] = tot;
    }
    __syncthreads();
    tot = sh[0];
    __syncthreads();
    return tot;
}

__device__ __forceinline__ float blockReduceMax(float val) {
    __shared__ float sh[32];
    int lane = threadIdx.x & 31, wid = threadIdx.x >> 5;
    #pragma unroll
    for (int o = 16; o > 0; o >>= 1) val = fmaxf(val, __shfl_xor_sync(0xffffffff, val, o));
    if (lane == 0) sh[wid] = val;
    __syncthreads();
    float tot = -1e30f;
    if (wid == 0) {
        tot = (lane < (int)(blockDim.x >> 5)) ? sh[lane] : -1e30f;
        #pragma unroll
        for (int o = 16; o > 0; o >>= 1) tot = fmaxf(tot, __shfl_xor_sync(0xffffffff, tot, o));
        if (lane == 0) sh[0] = tot;
    }
    __syncthreads();
    tot = sh[0];
    __syncthreads();
    return tot;
}

// ---------------- generic tiled SGEMM, 128x128x8, 256 thr, 8x8/thr ----------
// MODE: 0 = +bias[row]      (e0)
//       1 = plain store
//       2 = acc*z[row] + shortcut[row*N+col]   (e0=z, e1=shortcut)
//       3 = +bias[col]      (e0)
//       4 = +bias[col] + res[row*N+col]        (e0=bias, e1=res)
template<int MODE, bool TRANSA>
__global__ void __launch_bounds__(256)
gemm_tpl(const float* __restrict__ A, const float* __restrict__ B,
         float* __restrict__ C, int M, int N, int K,
         long long strA, long long strB, long long strC,
         const float* __restrict__ e0, const float* __restrict__ e1,
         long long strE0, long long strE1)
{
    int bz = blockIdx.z;
    A += (long long)bz * strA;
    B += (long long)bz * strB;
    C += (long long)bz * strC;
    const float* E0 = e0 ? e0 + (long long)bz * strE0 : nullptr;
    const float* E1 = e1 ? e1 + (long long)bz * strE1 : nullptr;

    __shared__ float As[8][128];
    __shared__ float Bs[8][128];
    int t  = threadIdx.x;
    int m0 = blockIdx.y * 128, n0 = blockIdx.x * 128;
    int tx = t & 15, ty = t >> 4;

    float acc[8][8];
    #pragma unroll
    for (int i = 0; i < 8; i++)
        #pragma unroll
        for (int j = 0; j < 8; j++) acc[i][j] = 0.f;

    for (int k0 = 0; k0 < K; k0 += 8) {
        if (TRANSA) {
            // A is (K, M) row-major with lda == M
            int kk = t >> 5, mm = (t & 31) * 4;
            float4 va = *reinterpret_cast<const float4*>(&A[(long long)(k0 + kk) * M + m0 + mm]);
            *reinterpret_cast<float4*>(&As[kk][mm]) = va;
        } else {
            // A is (M, K) row-major
            int mm = t >> 1, kk = (t & 1) * 4;
            float4 va = *reinterpret_cast<const float4*>(&A[(long long)(m0 + mm) * K + k0 + kk]);
            As[kk + 0][mm] = va.x; As[kk + 1][mm] = va.y;
            As[kk + 2][mm] = va.z; As[kk + 3][mm] = va.w;
        }
        {
            int kk = t >> 5, nn = (t & 31) * 4;
            float4 vb = *reinterpret_cast<const float4*>(&B[(long long)(k0 + kk) * N + n0 + nn]);
            *reinterpret_cast<float4*>(&Bs[kk][nn]) = vb;
        }
        __syncthreads();
        #pragma unroll
        for (int kk = 0; kk < 8; kk++) {
            float a[8], b[8];
            *reinterpret_cast<float4*>(&a[0]) = *reinterpret_cast<float4*>(&As[kk][ty * 8]);
            *reinterpret_cast<float4*>(&a[4]) = *reinterpret_cast<float4*>(&As[kk][ty * 8 + 4]);
            *reinterpret_cast<float4*>(&b[0]) = *reinterpret_cast<float4*>(&Bs[kk][tx * 8]);
            *reinterpret_cast<float4*>(&b[4]) = *reinterpret_cast<float4*>(&Bs[kk][tx * 8 + 4]);
            #pragma unroll
            for (int i = 0; i < 8; i++)
                #pragma unroll
                for (int j = 0; j < 8; j++)
                    acc[i][j] += a[i] * b[j];
        }
        __syncthreads();
    }

    #pragma unroll
    for (int i = 0; i < 8; i++) {
        int r = m0 + ty * 8 + i;
        #pragma unroll
        for (int j = 0; j < 8; j++) {
            int c = n0 + tx * 8 + j;
            float v = acc[i][j];
            if (MODE == 0) v += E0[r];
            if (MODE == 2) v = v * E0[r] + E1[(long long)r * N + c];
            if (MODE == 3) v += E0[c];
            if (MODE == 4) v += E0[c] + E1[(long long)r * N + c];
            C[(long long)r * N + c] = v;
        }
    }
}

// ---------------- transpose x (B,C,S) -> (B,S,C) ---------------------------
__global__ void transpose_x(const float* __restrict__ x, float* __restrict__ out)
{
    __shared__ float tile[32][33];
    int b  = blockIdx.z;
    int s0 = blockIdx.x * 32, c0 = blockIdx.y * 32;
    const float* xb = x   + (long long)b * CC * SS;
    float*       ob = out + (long long)b * SS * CC;
    int txx = threadIdx.x, tyy = threadIdx.y; // (32, 8)
    #pragma unroll
    for (int i = 0; i < 32; i += 8)
        tile[tyy + i][txx] = xb[(long long)(c0 + tyy + i) * SS + s0 + txx];
    __syncthreads();
    #pragma unroll
    for (int i = 0; i < 32; i += 8)
        ob[(long long)(s0 + tyy + i) * CC + c0 + txx] = tile[txx][tyy + i];
}

// ---------------- q: softmax over tokens (axis=1, strided columns) ---------
// grid (CC/32, NB), block (32, 16). Fuses +1e-6 and /softplus(scale).
__global__ void softmax_col_q(float* __restrict__ q, const float* __restrict__ scale)
{
    int b   = blockIdx.y;
    int col = blockIdx.x * 32 + threadIdx.x;
    int ry  = threadIdx.y;
    float* base = q + (long long)b * SS * CC + col;

    float m = -1e30f, s = 0.f;
    int i0 = ry * 256;
    for (int i = i0; i < i0 + 256; ++i) {
        float v  = base[(long long)i * CC];
        float mn = fmaxf(m, v);
        s = s * __expf(m - mn) + __expf(v - mn);
        m = mn;
    }
    __shared__ float sm[16][32], ss[16][32];
    sm[ry][threadIdx.x] = m; ss[ry][threadIdx.x] = s;
    __syncthreads();
    if (ry == 0) {
        float M = sm[0][threadIdx.x], S = ss[0][threadIdx.x];
        for (int r2 = 1; r2 < 16; r2++) {
            float m2 = sm[r2][threadIdx.x], s2 = ss[r2][threadIdx.x];
            float mn = fmaxf(M, m2);
            S = S * __expf(M - mn) + s2 * __expf(m2 - mn);
            M = mn;
        }
        sm[0][threadIdx.x] = M; ss[0][threadIdx.x] = S;
    }
    __syncthreads();
    float M   = sm[0][threadIdx.x];
    float inv = 1.f / ss[0][threadIdx.x];
    float isc = 1.f / log1pf(__expf(scale[col]));
    for (int i = i0; i < i0 + 256; ++i) {
        float v = base[(long long)i * CC];
        base[(long long)i * CC] = (__expf(v - M) * inv + 1e-6f) * isc;
    }
}

// ---------------- q row renorm: q = q^3 / ||q^3|| * ||q|| -------------------
__global__ void rownorm_pow3(float* __restrict__ buf)
{
    long long row = blockIdx.x;
    float* p = buf + row * CC;
    int t = threadIdx.x; // 128
    float4 f4 = *reinterpret_cast<const float4*>(p + t * 4);
    float v[4] = { f4.x, f4.y, f4.z, f4.w };
    float s1 = 0.f;
    #pragma unroll
    for (int r = 0; r < 4; r++) s1 += v[r] * v[r];
    s1 = blockReduceSum(s1);
    float u3[4];
    float s3 = 0.f;
    #pragma unroll
    for (int r = 0; r < 4; r++) { u3[r] = v[r] * v[r] * v[r]; s3 += u3[r] * u3[r]; }
    s3 = blockReduceSum(s3);
    float f = sqrtf(s1) / sqrtf(s3);
    float4 o = make_float4(u3[0] * f, u3[1] * f, u3[2] * f, u3[3] * f);
    *reinterpret_cast<float4*>(p + t * 4) = o;
}

// ---------------- k: row softmax + transform + renorm + ksum ---------------
__global__ void softmax_row_k(float* __restrict__ kbuf, const float* __restrict__ scale,
                              float* __restrict__ ksum)
{
    long long row = blockIdx.x;          // b*SS + i
    int b = (int)(row >> 12);
    float* p = kbuf + row * CC;
    int t = threadIdx.x; // 128
    float4 f4 = *reinterpret_cast<const float4*>(p + t * 4);
    float v[4] = { f4.x, f4.y, f4.z, f4.w };
    float mx = fmaxf(fmaxf(v[0], v[1]), fmaxf(v[2], v[3]));
    mx = blockReduceMax(mx);
    float se = 0.f;
    #pragma unroll
    for (int r = 0; r < 4; r++) se += __expf(v[r] - mx);
    se = blockReduceSum(se);
    float inv = 1.f / se;
    float u[4];
    #pragma unroll
    for (int r = 0; r < 4; r++) {
        float isc = 1.f / log1pf(__expf(scale[t * 4 + r]));
        u[r] = (__expf(v[r] - mx) * inv + 1e-6f) * isc;
    }
    float s1 = 0.f;
    #pragma unroll
    for (int r = 0; r < 4; r++) s1 += u[r] * u[r];
    s1 = blockReduceSum(s1);
    float u3[4];
    float s3 = 0.f;
    #pragma unroll
    for (int r = 0; r < 4; r++) { u3[r] = u[r] * u[r] * u[r]; s3 += u3[r] * u3[r]; }
    s3 = blockReduceSum(s3);
    float f = sqrtf(s1) / sqrtf(s3);
    float o[4];
    #pragma unroll
    for (int r = 0; r < 4; r++) o[r] = u3[r] * f;
    *reinterpret_cast<float4*>(p + t * 4) = make_float4(o[0], o[1], o[2], o[3]);
    #pragma unroll
    for (int r = 0; r < 4; r++)
        atomicAdd(&ksum[b * CC + t * 4 + r], o[r]);
}

__global__ void zero_ksum(float* __restrict__ ksum)
{
    int i = blockIdx.x * blockDim.x + threadIdx.x;
    if (i < NB * CC) ksum[i] = 0.f;
}

// ---------------- z[b,i] = 1/(q_row . ksum_b + 1e-6) ------------------------
__global__ void compute_z(const float* __restrict__ q, const float* __restrict__ ksum,
                          float* __restrict__ z)
{
    long long row = (long long)blockIdx.x * 8 + (threadIdx.x >> 5);
    int lane = threadIdx.x & 31;
    int b = (int)(row >> 12);
    const float* p  = q + row * CC;
    const float* ks = ksum + b * CC;
    float s = 0.f;
    for (int c = lane; c < CC; c += 32) s += p[c] * ks[c];
    #pragma unroll
    for (int o = 16; o > 0; o >>= 1) s += __shfl_xor_sync(0xffffffff, s, o);
    if (lane == 0) z[row] = 1.f / (s + 1e-6f);
}

// ---------------- LayerNorm over C=512 --------------------------------------
__global__ void layernorm512(const float* __restrict__ in, float* __restrict__ out,
                             const float* __restrict__ g, const float* __restrict__ bta)
{
    long long row = blockIdx.x;
    const float* p = in + row * CC;
    int t = threadIdx.x; // 128
    float4 f4 = *reinterpret_cast<const float4*>(p + t * 4);
    float v[4] = { f4.x, f4.y, f4.z, f4.w };
    float s = v[0] + v[1] + v[2] + v[3];
    s = blockReduceSum(s);
    float mean = s * (1.f / (float)CC);
    float s2 = 0.f;
    #pragma unroll
    for (int r = 0; r < 4; r++) { float d = v[r] - mean; s2 += d * d; }
    s2 = blockReduceSum(s2);
    float rstd = rsqrtf(s2 * (1.f / (float)CC) + 1e-5f);
    float o[4];
    #pragma unroll
    for (int r = 0; r < 4; r++) {
        int c = t * 4 + r;
        o[r] = (v[r] - mean) * rstd * g[c] + bta[c];
    }
    *reinterpret_cast<float4*>(out + row * CC + t * 4) = make_float4(o[0], o[1], o[2], o[3]);
}

// ---------------- depthwise 3x3 + residual + LN(HID) + exact GELU ----------
__global__ void dw_ln_gelu(const float* __restrict__ a, const float* __restrict__ w,
                           const float* __restrict__ wb, const float* __restrict__ g,
                           const float* __restrict__ beta, float* __restrict__ out)
{
    long long idx = blockIdx.x;          // b*SS + s
    int b = (int)(idx >> 12);
    int s = (int)(idx & 4095);
    int y = s >> 6, x = s & 63;
    int t = threadIdx.x;                 // 256, each handles 8 channels
    const float* ab = a + (long long)b * SS * HD;

    float val[8];
    float sum = 0.f;
    #pragma unroll
    for (int r = 0; r < 8; r++) {
        int h = r * 256 + t;
        float acc = wb[h];
        #pragma unroll
        for (int ky = 0; ky < 3; ky++) {
            int yy = y + ky - 1;
            if (yy < 0 || yy > 63) continue;
            #pragma unroll
            for (int kx = 0; kx < 3; kx++) {
                int xx = x + kx - 1;
                if (xx < 0 || xx > 63) continue;
                acc += w[h * 9 + ky * 3 + kx] * ab[((long long)(yy * 64 + xx)) * HD + h];
            }
        }
        acc += ab[(long long)s * HD + h];      // + a (skip before LN)
        val[r] = acc;
        sum += acc;
    }
    sum = blockReduceSum(sum);
    float mean = sum * (1.f / (float)HD);
    float s2 = 0.f;
    #pragma unroll
    for (int r = 0; r < 8; r++) { float d = val[r] - mean; s2 += d * d; }
    s2 = blockReduceSum(s2);
    float rstd = rsqrtf(s2 * (1.f / (float)HD) + 1e-5f);
    #pragma unroll
    for (int r = 0; r < 8; r++) {
        int h = r * 256 + t;
        float yv = (val[r] - mean) * rstd * g[h] + beta[h];
        float ge = 0.5f * yv * (1.f + erff(yv * 0.70710678118654752f));
        out[idx * HD + h] = ge;
    }
}

// ---------------- launch ----------------------------------------------------
extern "C" void kernel_launch(void* const* d_in, const int* in_sizes, int n_in,
                              void* d_out, int out_size)
{
    const float* x      = (const float*)d_in[0];
    const float* Wq     = (const float*)d_in[1];
    const float* bq     = (const float*)d_in[2];
    const float* Wk     = (const float*)d_in[3];
    const float* bk     = (const float*)d_in[4];
    const float* Wv     = (const float*)d_in[5];
    const float* bv     = (const float*)d_in[6];
    const float* scale  = (const float*)d_in[7];
    const float* fc1_w  = (const float*)d_in[8];
    const float* fc1_b  = (const float*)d_in[9];
    const float* dw_w   = (const float*)d_in[10];
    const float* dw_b   = (const float*)d_in[11];
    const float* fc2_w  = (const float*)d_in[12];
    const float* fc2_b  = (const float*)d_in[13];
    const float* ln1_g  = (const float*)d_in[14];
    const float* ln1_b  = (const float*)d_in[15];
    const float* lnm_g  = (const float*)d_in[16];
    const float* lnm_b  = (const float*)d_in[17];
    float* out = (float*)d_out;

    void *pq, *pk, *pv, *psc, *penh, *pt, *pa, *pax, *pkv, *pksum, *pz;
    cudaGetSymbolAddress(&pq,   g_q);
    cudaGetSymbolAddress(&pk,   g_k);
    cudaGetSymbolAddress(&pv,   g_v);
    cudaGetSymbolAddress(&psc,  g_sc);
    cudaGetSymbolAddress(&penh, g_enh);
    cudaGetSymbolAddress(&pt,   g_t);
    cudaGetSymbolAddress(&pa,   g_a);
    cudaGetSymbolAddress(&pax,  g_ax);
    cudaGetSymbolAddress(&pkv,  g_kv);
    cudaGetSymbolAddress(&pksum,g_ksum);
    cudaGetSymbolAddress(&pz,   g_z);

    const long long BS = (long long)CC * SS;      // per-batch qkv/feature stride
    const long long KVS = (long long)CC * CC;

    // 1. shortcut = x^T per batch
    transpose_x<<<dim3(SS/32, CC/32, NB), dim3(32, 8)>>>(x, (float*)psc);

    // 2. qkv GEMMs: (512x512) @ (512x4096) per batch, bias by row(out channel)
    gemm_tpl<0,false><<<dim3(SS/128, CC/128, NB), 256>>>(Wq, x, (float*)pq, CC, SS, CC,
        0, BS, BS, bq, nullptr, 0, 0);
    gemm_tpl<0,false><<<dim3(SS/128, CC/128, NB), 256>>>(Wk, x, (float*)pk, CC, SS, CC,
        0, BS, BS, bk, nullptr, 0, 0);
    gemm_tpl<0,false><<<dim3(SS/128, CC/128, NB), 256>>>(Wv, x, (float*)pv, CC, SS, CC,
        0, BS, BS, bv, nullptr, 0, 0);

    // 3. q path: column softmax (+eps, /softplus), then row renorm^3
    softmax_col_q<<<dim3(CC/32, NB), dim3(32, 16)>>>((float*)pq, scale);
    rownorm_pow3<<<NB*SS, 128>>>((float*)pq);

    // 4. k path: row softmax + transform + renorm + ksum (atomics)
    zero_ksum<<<4, 1024>>>((float*)pksum);
    softmax_row_k<<<NB*SS, 128>>>((float*)pk, scale, (float*)pksum);

    // 5. kv = k^T v per batch (512x512, K=4096)
    gemm_tpl<1,true><<<dim3(CC/128, CC/128, NB), 256>>>((float*)pk, (float*)pv, (float*)pkv,
        CC, CC, SS, BS, BS, KVS, nullptr, nullptr, 0, 0);

    // 6. z
    compute_z<<<NB*SS/8, 256>>>((float*)pq, (float*)pksum, (float*)pz);

    // 7. enhanced = shortcut + z * (q @ kv)
    gemm_tpl<2,false><<<dim3(CC/128, SS/128, NB), 256>>>((float*)pq, (float*)pkv, (float*)penh,
        SS, CC, CC, BS, KVS, BS, (float*)pz, (float*)psc, SS, BS);

    // 8. t = LN(enhanced)
    layernorm512<<<NB*SS, 128>>>((float*)penh, (float*)pt, lnm_g, lnm_b);

    // 9. a = t @ fc1_w + fc1_b   (32768 x 2048, K=512)
    gemm_tpl<3,false><<<dim3(HD/128, (NB*SS)/128, 1), 256>>>((float*)pt, fc1_w, (float*)pa,
        NB*SS, HD, CC, 0, 0, 0, fc1_b, nullptr, 0, 0);

    // 10. ax = gelu(LN(dwconv3x3(a) + dw_b + a))
    dw_ln_gelu<<<NB*SS, 256>>>((float*)pa, dw_w, dw_b, ln1_g, ln1_b, (float*)pax);

    // 11. out = enhanced + ax @ fc2_w + fc2_b   (32768 x 512, K=2048)
    gemm_tpl<4,false><<<dim3(CC/128, (NB*SS)/128, 1), 256>>>((float*)pax, fc2_w, out,
        NB*SS, CC, HD, 0, 0, 0, fc2_b, (float*)penh, 0, 0);
}

// round 3
// speedup vs baseline: 1.6230x; 1.6230x over previous
#include <cuda_runtime.h>
#include <cuda_bf16.h>
#include <math.h>
#include <stdint.h>

// Problem dims
#define NB 8
#define CC 512
#define SS 4096     // N = H*W tokens
#define HD 2048     // HID = 4*C
#define HH 64

// ---------------- scratch (device globals; no allocation allowed) ----------
__device__ float g_q  [(long long)NB*CC*SS];   // 64MB, raw-reshape (B, N, C) view
__device__ float g_k  [(long long)NB*CC*SS];
__device__ float g_kt [(long long)NB*CC*SS];   // k transposed to (C, S)
__device__ float g_v  [(long long)NB*CC*SS];
__device__ float g_sc [(long long)NB*SS*CC];   // shortcut = x transposed (B, N, C)
__device__ float g_enh[(long long)NB*SS*CC];
__device__ float g_t  [(long long)NB*SS*CC];
__device__ float g_a  [(long long)NB*SS*HD];   // 256MB
__device__ float g_ax [(long long)NB*SS*HD];   // 256MB
__device__ float g_kv [(long long)NB*CC*CC];
__device__ float g_ksum[NB*CC];
__device__ float g_z  [NB*SS];

// ---------------- helpers ---------------------------------------------------
__device__ __forceinline__ float blockReduceSum(float val) {
    __shared__ float sh[32];
    int lane = threadIdx.x & 31, wid = threadIdx.x >> 5;
    #pragma unroll
    for (int o = 16; o > 0; o >>= 1) val += __shfl_xor_sync(0xffffffff, val, o);
    if (lane == 0) sh[wid] = val;
    __syncthreads();
    float tot = 0.f;
    if (wid == 0) {
        tot = (lane < (int)(blockDim.x >> 5)) ? sh[lane] : 0.f;
        #pragma unroll
        for (int o = 16; o > 0; o >>= 1) tot += __shfl_xor_sync(0xffffffff, tot, o);
        if (lane == 0) sh[0] = tot;
    }
    __syncthreads();
    tot = sh[0];
    __syncthreads();
    return tot;
}

__device__ __forceinline__ float blockReduceMax(float val) {
    __shared__ float sh[32];
    int lane = threadIdx.x & 31, wid = threadIdx.x >> 5;
    #pragma unroll
    for (int o = 16; o > 0; o >>= 1) val = fmaxf(val, __shfl_xor_sync(0xffffffff, val, o));
    if (lane == 0) sh[wid] = val;
    __syncthreads();
    float tot = -1e30f;
    if (wid == 0) {
        tot = (lane < (int)(blockDim.x >> 5)) ? sh[lane] : -1e30f;
        #pragma unroll
        for (int o = 16; o > 0; o >>= 1) tot = fmaxf(tot, __shfl_xor_sync(0xffffffff, tot, o));
        if (lane == 0) sh[0] = tot;
    }
    __syncthreads();
    tot = sh[0];
    __syncthreads();
    return tot;
}

// cvt.rna.tf32.f32 needs a .b32 (register) destination
__device__ __forceinline__ float cvt_tf32(float v) {
    uint32_t u;
    asm("cvt.rna.tf32.f32 %0, %1;" : "=r"(u) : "f"(v));
    return __uint_as_float(u);
}
__device__ __forceinline__ void cvt_split(float v, float& h, float& l) {
    h = cvt_tf32(v);
    l = cvt_tf32(v - h);
}

#define MMA_TF32(d, a, b) \
    asm volatile("mma.sync.aligned.m16n8k8.row.col.f32.tf32.tf32.f32 " \
        "{%0,%1,%2,%3},{%4,%5,%6,%7},{%8,%9},{%0,%1,%2,%3};" \
        : "+f"(d[0]), "+f"(d[1]), "+f"(d[2]), "+f"(d[3]) \
        : "r"(a[0]), "r"(a[1]), "r"(a[2]), "r"(a[3]), "r"(b[0]), "r"(b[1]))

// ---------------- tensor-core TF32 GEMM: 128x128 tile, BK=16, 256 thr -------
// MODE: 0 = +bias[row] (e0)
//       1 = plain
//       2 = acc*z[row] + shortcut[row*N+col]   (e0=z, e1=shortcut)
//       3 = +bias[col] (e0)
//       4 = +bias[col] + res[row*N+col]        (e0=bias, e1=res)
// SPLIT: 3xTF32 (hi/lo planes) for ~fp32 accuracy.
template<int MODE, bool SPLIT>
__global__ void __launch_bounds__(256)
gemm_tc(const float* __restrict__ A, const float* __restrict__ B,
        float* __restrict__ C, int M, int N, int K,
        long long strA, long long strB, long long strC,
        const float* __restrict__ e0, const float* __restrict__ e1,
        long long strE0, long long strE1)
{
    constexpr int PL = SPLIT ? 2 : 1;
    __shared__ float As[PL][128][20];    // row pad 20 floats (80B, 16B-aligned rows)
    __shared__ float Bs[PL][16][136];    // row pad 136 floats

    const int bz = blockIdx.z;
    A += (long long)bz * strA;
    B += (long long)bz * strB;
    C += (long long)bz * strC;
    const float* E0 = e0 ? e0 + (long long)bz * strE0 : nullptr;
    const float* E1 = e1 ? e1 + (long long)bz * strE1 : nullptr;

    const int t    = threadIdx.x;
    const int lane = t & 31, warp = t >> 5;
    const int m0   = blockIdx.y * 128, n0 = blockIdx.x * 128;
    const int wm0  = (warp & 1) * 64;    // 2 warps in M
    const int wn0  = (warp >> 1) * 32;   // 4 warps in N

    // gmem load assignment
    const int lam = t >> 1, lah = (t & 1) * 8;   // A: row in tile, col-offset
    const int lbk = t >> 4, lbn = (t & 15) * 8;  // B: k row, n-offset

    float acc[4][4][4];
    #pragma unroll
    for (int i = 0; i < 4; i++)
        #pragma unroll
        for (int j = 0; j < 4; j++)
            #pragma unroll
            for (int r = 0; r < 4; r++) acc[i][j][r] = 0.f;

    // ldmatrix base address pieces
    uint32_t sA_u32 = (uint32_t)__cvta_generic_to_shared(&As[0][0][0]);
    const int aRow    = wm0 + (lane & 15);
    const int aColSel = (lane >> 4) << 2;      // 0 or 4

    const int bkRow = lane & 3;
    const int bnCol = wn0 + (lane >> 2);

    const int nk = K >> 4;

    float4 ra0, ra1, rb0, rb1;
    {
        const float* ap = A + (long long)(m0 + lam) * K + lah;
        ra0 = *reinterpret_cast<const float4*>(ap);
        ra1 = *reinterpret_cast<const float4*>(ap + 4);
        const float* bp = B + (long long)lbk * N + n0 + lbn;
        rb0 = *reinterpret_cast<const float4*>(bp);
        rb1 = *reinterpret_cast<const float4*>(bp + 4);
    }

    for (int kt = 0; kt < nk; kt++) {
        // ---- stage regs -> smem with tf32 conversion (and split) ----
        {
            const float* va = reinterpret_cast<const float*>(&ra0);
            #pragma unroll
            for (int j = 0; j < 4; j++) {
                if (SPLIT) { float h, l; cvt_split(va[j], h, l); As[0][lam][lah + j] = h; As[PL-1][lam][lah + j] = l; }
                else       { As[0][lam][lah + j] = cvt_tf32(va[j]); }
            }
            const float* vb = reinterpret_cast<const float*>(&ra1);
            #pragma unroll
            for (int j = 0; j < 4; j++) {
                if (SPLIT) { float h, l; cvt_split(vb[j], h, l); As[0][lam][lah + 4 + j] = h; As[PL-1][lam][lah + 4 + j] = l; }
                else       { As[0][lam][lah + 4 + j] = cvt_tf32(vb[j]); }
            }
            const float* vc = reinterpret_cast<const float*>(&rb0);
            #pragma unroll
            for (int j = 0; j < 4; j++) {
                if (SPLIT) { float h, l; cvt_split(vc[j], h, l); Bs[0][lbk][lbn + j] = h; Bs[PL-1][lbk][lbn + j] = l; }
                else       { Bs[0][lbk][lbn + j] = cvt_tf32(vc[j]); }
            }
            const float* vd = reinterpret_cast<const float*>(&rb1);
            #pragma unroll
            for (int j = 0; j < 4; j++) {
                if (SPLIT) { float h, l; cvt_split(vd[j], h, l); Bs[0][lbk][lbn + 4 + j] = h; Bs[PL-1][lbk][lbn + 4 + j] = l; }
                else       { Bs[0][lbk][lbn + 4 + j] = cvt_tf32(vd[j]); }
            }
        }
        __syncthreads();

        // ---- prefetch next tile into regs (latency overlapped with mma) ----
        if (kt + 1 < nk) {
            int k0 = (kt + 1) << 4;
            const float* ap = A + (long long)(m0 + lam) * K + k0 + lah;
            ra0 = *reinterpret_cast<const float4*>(ap);
            ra1 = *reinterpret_cast<const float4*>(ap + 4);
            const float* bp = B + (long long)(k0 + lbk) * N + n0 + lbn;
            rb0 = *reinterpret_cast<const float4*>(bp);
            rb1 = *reinterpret_cast<const float4*>(bp + 4);
        }

        // ---- compute: 2 x k8 ----
        #pragma unroll
        for (int k8 = 0; k8 < 16; k8 += 8) {
            uint32_t af[PL][4][4];
            #pragma unroll
            for (int p = 0; p < PL; p++)
                #pragma unroll
                for (int mt = 0; mt < 4; mt++) {
                    uint32_t addr = sA_u32 +
                        ((uint32_t)(p * 2560 + (aRow + mt * 16) * 20 + k8 + aColSel) << 2);
                    asm volatile("ldmatrix.sync.aligned.m8n8.x4.shared.b16 {%0,%1,%2,%3}, [%4];"
                        : "=r"(af[p][mt][0]), "=r"(af[p][mt][1]), "=r"(af[p][mt][2]), "=r"(af[p][mt][3])
                        : "r"(addr) : "memory");
                }
            uint32_t bf[PL][4][2];
            #pragma unroll
            for (int p = 0; p < PL; p++)
                #pragma unroll
                for (int nt = 0; nt < 4; nt++) {
                    bf[p][nt][0] = __float_as_uint(Bs[p][k8 + bkRow    ][bnCol + nt * 8]);
                    bf[p][nt][1] = __float_as_uint(Bs[p][k8 + bkRow + 4][bnCol + nt * 8]);
                }
            #pragma unroll
            for (int mt = 0; mt < 4; mt++)
                #pragma unroll
                for (int nt = 0; nt < 4; nt++) {
                    MMA_TF32(acc[mt][nt], af[0][mt], bf[0][nt]);
                    if (SPLIT) {
                        MMA_TF32(acc[mt][nt], af[0][mt], bf[PL-1][nt]);
                        MMA_TF32(acc[mt][nt], af[PL-1][mt], bf[0][nt]);
                    }
                }
        }
        __syncthreads();
    }

    // ---- epilogue ----
    #pragma unroll
    for (int mt = 0; mt < 4; mt++) {
        #pragma unroll
        for (int half = 0; half < 2; half++) {
            int r = m0 + wm0 + mt * 16 + (lane >> 2) + half * 8;
            #pragma unroll
            for (int nt = 0; nt < 4; nt++) {
                int c = n0 + wn0 + nt * 8 + (lane & 3) * 2;
                float v0 = acc[mt][nt][half * 2 + 0];
                float v1 = acc[mt][nt][half * 2 + 1];
                long long off = (long long)r * N + c;
                if (MODE == 0) { float b = E0[r]; v0 += b; v1 += b; }
                if (MODE == 2) {
                    float zz = E0[r];
                    float2 s = *reinterpret_cast<const float2*>(&E1[off]);
                    v0 = v0 * zz + s.x; v1 = v1 * zz + s.y;
                }
                if (MODE == 3) { v0 += E0[c]; v1 += E0[c + 1]; }
                if (MODE == 4) {
                    float2 s = *reinterpret_cast<const float2*>(&E1[off]);
                    v0 += E0[c] + s.x; v1 += E0[c + 1] + s.y;
                }
                *reinterpret_cast<float2*>(&C[off]) = make_float2(v0, v1);
            }
        }
    }
}

// ---------------- transpose x (B,C,S) -> (B,S,C) ---------------------------
__global__ void transpose_x(const float* __restrict__ x, float* __restrict__ out)
{
    __shared__ float tile[32][33];
    int b  = blockIdx.z;
    int s0 = blockIdx.x * 32, c0 = blockIdx.y * 32;
    const float* xb = x   + (long long)b * CC * SS;
    float*       ob = out + (long long)b * SS * CC;
    int txx = threadIdx.x, tyy = threadIdx.y; // (32, 8)
    #pragma unroll
    for (int i = 0; i < 32; i += 8)
        tile[tyy + i][txx] = xb[(long long)(c0 + tyy + i) * SS + s0 + txx];
    __syncthreads();
    #pragma unroll
    for (int i = 0; i < 32; i += 8)
        ob[(long long)(s0 + tyy + i) * CC + c0 + txx] = tile[txx][tyy + i];
}

// ---------------- transpose (B,S,C) -> (B,C,S)  (for kT) -------------------
__global__ void transpose_sc(const float* __restrict__ in, float* __restrict__ out)
{
    __shared__ float tile[32][33];
    int b  = blockIdx.z;
    int s0 = blockIdx.x * 32, c0 = blockIdx.y * 32;
    const float* ib = in  + (long long)b * SS * CC;
    float*       ob = out + (long long)b * CC * SS;
    int txx = threadIdx.x, tyy = threadIdx.y; // (32, 8)
    #pragma unroll
    for (int i = 0; i < 32; i += 8)
        tile[tyy + i][txx] = ib[(long long)(s0 + tyy + i) * CC + c0 + txx];
    __syncthreads();
    #pragma unroll
    for (int i = 0; i < 32; i += 8)
        ob[(long long)(c0 + tyy + i) * SS + s0 + txx] = tile[txx][tyy + i];
}

// ---------------- q: softmax over tokens (axis=1, strided columns) ---------
__global__ void softmax_col_q(float* __restrict__ q, const float* __restrict__ scale)
{
    int b   = blockIdx.y;
    int col = blockIdx.x * 32 + threadIdx.x;
    int ry  = threadIdx.y;
    float* base = q + (long long)b * SS * CC + col;

    float m = -1e30f, s = 0.f;
    int i0 = ry * 256;
    for (int i = i0; i < i0 + 256; ++i) {
        float v  = base[(long long)i * CC];
        float mn = fmaxf(m, v);
        s = s * __expf(m - mn) + __expf(v - mn);
        m = mn;
    }
    __shared__ float sm[16][32], ss[16][32];
    sm[ry][threadIdx.x] = m; ss[ry][threadIdx.x] = s;
    __syncthreads();
    if (ry == 0) {
        float M = sm[0][threadIdx.x], S = ss[0][threadIdx.x];
        for (int r2 = 1; r2 < 16; r2++) {
            float m2 = sm[r2][threadIdx.x], s2 = ss[r2][threadIdx.x];
            float mn = fmaxf(M, m2);
            S = S * __expf(M - mn) + s2 * __expf(m2 - mn);
            M = mn;
        }
        sm[0][threadIdx.x] = M; ss[0][threadIdx.x] = S;
    }
    __syncthreads();
    float M   = sm[0][threadIdx.x];
    float inv = 1.f / ss[0][threadIdx.x];
    float isc = 1.f / log1pf(__expf(scale[col]));
    for (int i = i0; i < i0 + 256; ++i) {
        float v = base[(long long)i * CC];
        base[(long long)i * CC] = (__expf(v - M) * inv + 1e-6f) * isc;
    }
}

// ---------------- q row renorm: q = q^3 / ||q^3|| * ||q|| -------------------
__global__ void rownorm_pow3(float* __restrict__ buf)
{
    long long row = blockIdx.x;
    float* p = buf + row * CC;
    int t = threadIdx.x; // 128
    float4 f4 = *reinterpret_cast<const float4*>(p + t * 4);
    float v[4] = { f4.x, f4.y, f4.z, f4.w };
    float s1 = 0.f;
    #pragma unroll
    for (int r = 0; r < 4; r++) s1 += v[r] * v[r];
    s1 = blockReduceSum(s1);
    float u3[4];
    float s3 = 0.f;
    #pragma unroll
    for (int r = 0; r < 4; r++) { u3[r] = v[r] * v[r] * v[r]; s3 += u3[r] * u3[r]; }
    s3 = blockReduceSum(s3);
    float f = sqrtf(s1) / sqrtf(s3);
    float4 o = make_float4(u3[0] * f, u3[1] * f, u3[2] * f, u3[3] * f);
    *reinterpret_cast<float4*>(p + t * 4) = o;
}

// ---------------- k: row softmax + transform + renorm + ksum ---------------
__global__ void softmax_row_k(float* __restrict__ kbuf, const float* __restrict__ scale,
                              float* __restrict__ ksum)
{
    long long row = blockIdx.x;          // b*SS + i
    int b = (int)(row >> 12);
    float* p = kbuf + row * CC;
    int t = threadIdx.x; // 128
    float4 f4 = *reinterpret_cast<const float4*>(p + t * 4);
    float v[4] = { f4.x, f4.y, f4.z, f4.w };
    float mx = fmaxf(fmaxf(v[0], v[1]), fmaxf(v[2], v[3]));
    mx = blockReduceMax(mx);
    float se = 0.f;
    #pragma unroll
    for (int r = 0; r < 4; r++) se += __expf(v[r] - mx);
    se = blockReduceSum(se);
    float inv = 1.f / se;
    float u[4];
    #pragma unroll
    for (int r = 0; r < 4; r++) {
        float isc = 1.f / log1pf(__expf(scale[t * 4 + r]));
        u[r] = (__expf(v[r] - mx) * inv + 1e-6f) * isc;
    }
    float s1 = 0.f;
    #pragma unroll
    for (int r = 0; r < 4; r++) s1 += u[r] * u[r];
    s1 = blockReduceSum(s1);
    float u3[4];
    float s3 = 0.f;
    #pragma unroll
    for (int r = 0; r < 4; r++) { u3[r] = u[r] * u[r] * u[r]; s3 += u3[r] * u3[r]; }
    s3 = blockReduceSum(s3);
    float f = sqrtf(s1) / sqrtf(s3);
    float o[4];
    #pragma unroll
    for (int r = 0; r < 4; r++) o[r] = u3[r] * f;
    *reinterpret_cast<float4*>(p + t * 4) = make_float4(o[0], o[1], o[2], o[3]);
    #pragma unroll
    for (int r = 0; r < 4; r++)
        atomicAdd(&ksum[b * CC + t * 4 + r], o[r]);
}

__global__ void zero_ksum(float* __restrict__ ksum)
{
    int i = blockIdx.x * blockDim.x + threadIdx.x;
    if (i < NB * CC) ksum[i] = 0.f;
}

// ---------------- z[b,i] = 1/(q_row . ksum_b + 1e-6) ------------------------
__global__ void compute_z(const float* __restrict__ q, const float* __restrict__ ksum,
                          float* __restrict__ z)
{
    long long row = (long long)blockIdx.x * 8 + (threadIdx.x >> 5);
    int lane = threadIdx.x & 31;
    int b = (int)(row >> 12);
    const float* p  = q + row * CC;
    const float* ks = ksum + b * CC;
    float s = 0.f;
    for (int c = lane; c < CC; c += 32) s += p[c] * ks[c];
    #pragma unroll
    for (int o = 16; o > 0; o >>= 1) s += __shfl_xor_sync(0xffffffff, s, o);
    if (lane == 0) z[row] = 1.f / (s + 1e-6f);
}

// ---------------- LayerNorm over C=512 --------------------------------------
__global__ void layernorm512(const float* __restrict__ in, float* __restrict__ out,
                             const float* __restrict__ g, const float* __restrict__ bta)
{
    long long row = blockIdx.x;
    const float* p = in + row * CC;
    int t = threadIdx.x; // 128
    float4 f4 = *reinterpret_cast<const float4*>(p + t * 4);
    float v[4] = { f4.x, f4.y, f4.z, f4.w };
    float s = v[0] + v[1] + v[2] + v[3];
    s = blockReduceSum(s);
    float mean = s * (1.f / (float)CC);
    float s2 = 0.f;
    #pragma unroll
    for (int r = 0; r < 4; r++) { float d = v[r] - mean; s2 += d * d; }
    s2 = blockReduceSum(s2);
    float rstd = rsqrtf(s2 * (1.f / (float)CC) + 1e-5f);
    float o[4];
    #pragma unroll
    for (int r = 0; r < 4; r++) {
        int c = t * 4 + r;
        o[r] = (v[r] - mean) * rstd * g[c] + bta[c];
    }
    *reinterpret_cast<float4*>(out + row * CC + t * 4) = make_float4(o[0], o[1], o[2], o[3]);
}

// ---------------- depthwise 3x3 + residual + LN(HID) + exact GELU ----------
__global__ void dw_ln_gelu(const float* __restrict__ a, const float* __restrict__ w,
                           const float* __restrict__ wb, const float* __restrict__ g,
                           const float* __restrict__ beta, float* __restrict__ out)
{
    long long idx = blockIdx.x;          // b*SS + s
    int b = (int)(idx >> 12);
    int s = (int)(idx & 4095);
    int y = s >> 6, x = s & 63;
    int t = threadIdx.x;                 // 256, each handles 8 channels
    const float* ab = a + (long long)b * SS * HD;

    float val[8];
    float sum = 0.f;
    #pragma unroll
    for (int r = 0; r < 8; r++) {
        int h = r * 256 + t;
        float acc = wb[h];
        #pragma unroll
        for (int ky = 0; ky < 3; ky++) {
            int yy = y + ky - 1;
            if (yy < 0 || yy > 63) continue;
            #pragma unroll
            for (int kx = 0; kx < 3; kx++) {
                int xx = x + kx - 1;
                if (xx < 0 || xx > 63) continue;
                acc += w[h * 9 + ky * 3 + kx] * ab[((long long)(yy * 64 + xx)) * HD + h];
            }
        }
        acc += ab[(long long)s * HD + h];      // + a (skip before LN)
        val[r] = acc;
        sum += acc;
    }
    sum = blockReduceSum(sum);
    float mean = sum * (1.f / (float)HD);
    float s2 = 0.f;
    #pragma unroll
    for (int r = 0; r < 8; r++) { float d = val[r] - mean; s2 += d * d; }
    s2 = blockReduceSum(s2);
    float rstd = rsqrtf(s2 * (1.f / (float)HD) + 1e-5f);
    #pragma unroll
    for (int r = 0; r < 8; r++) {
        int h = r * 256 + t;
        float yv = (val[r] - mean) * rstd * g[h] + beta[h];
        float ge = 0.5f * yv * (1.f + erff(yv * 0.70710678118654752f));
        out[idx * HD + h] = ge;
    }
}

// ---------------- launch ----------------------------------------------------
extern "C" void kernel_launch(void* const* d_in, const int* in_sizes, int n_in,
                              void* d_out, int out_size)
{
    const float* x      = (const float*)d_in[0];
    const float* Wq     = (const float*)d_in[1];
    const float* bq     = (const float*)d_in[2];
    const float* Wk     = (const float*)d_in[3];
    const float* bk     = (const float*)d_in[4];
    const float* Wv     = (const float*)d_in[5];
    const float* bv     = (const float*)d_in[6];
    const float* scale  = (const float*)d_in[7];
    const float* fc1_w  = (const float*)d_in[8];
    const float* fc1_b  = (const float*)d_in[9];
    const float* dw_w   = (const float*)d_in[10];
    const float* dw_b   = (const float*)d_in[11];
    const float* fc2_w  = (const float*)d_in[12];
    const float* fc2_b  = (const float*)d_in[13];
    const float* ln1_g  = (const float*)d_in[14];
    const float* ln1_b  = (const float*)d_in[15];
    const float* lnm_g  = (const float*)d_in[16];
    const float* lnm_b  = (const float*)d_in[17];
    float* out = (float*)d_out;

    void *pq, *pk, *pkt, *pv, *psc, *penh, *pt, *pa, *pax, *pkv, *pksum, *pz;
    cudaGetSymbolAddress(&pq,   g_q);
    cudaGetSymbolAddress(&pk,   g_k);
    cudaGetSymbolAddress(&pkt,  g_kt);
    cudaGetSymbolAddress(&pv,   g_v);
    cudaGetSymbolAddress(&psc,  g_sc);
    cudaGetSymbolAddress(&penh, g_enh);
    cudaGetSymbolAddress(&pt,   g_t);
    cudaGetSymbolAddress(&pa,   g_a);
    cudaGetSymbolAddress(&pax,  g_ax);
    cudaGetSymbolAddress(&pkv,  g_kv);
    cudaGetSymbolAddress(&pksum,g_ksum);
    cudaGetSymbolAddress(&pz,   g_z);

    const long long BS  = (long long)CC * SS;
    const long long KVS = (long long)CC * CC;

    // 1. shortcut = x^T per batch
    transpose_x<<<dim3(SS/32, CC/32, NB), dim3(32, 8)>>>(x, (float*)psc);

    // 2. qkv GEMMs (split-tf32 for precision): (512x512)@(512x4096), bias[row]
    gemm_tc<0,true><<<dim3(SS/128, CC/128, NB), 256>>>(Wq, x, (float*)pq, CC, SS, CC,
        0, BS, BS, bq, nullptr, 0, 0);
    gemm_tc<0,true><<<dim3(SS/128, CC/128, NB), 256>>>(Wk, x, (float*)pk, CC, SS, CC,
        0, BS, BS, bk, nullptr, 0, 0);
    gemm_tc<0,true><<<dim3(SS/128, CC/128, NB), 256>>>(Wv, x, (float*)pv, CC, SS, CC,
        0, BS, BS, bv, nullptr, 0, 0);

    // 3. q path: column softmax, then row renorm^3
    softmax_col_q<<<dim3(CC/32, NB), dim3(32, 16)>>>((float*)pq, scale);
    rownorm_pow3<<<NB*SS, 128>>>((float*)pq);

    // 4. k path: row softmax + transform + renorm + ksum
    zero_ksum<<<4, 1024>>>((float*)pksum);
    softmax_row_k<<<NB*SS, 128>>>((float*)pk, scale, (float*)pksum);

    // 4b. kT = transpose(k): (S,C) -> (C,S), so kv GEMM is NN-form
    transpose_sc<<<dim3(SS/32, CC/32, NB), dim3(32, 8)>>>((float*)pk, (float*)pkt);

    // 5. kv = kT @ v  (512x512, K=4096)
    gemm_tc<1,false><<<dim3(CC/128, CC/128, NB), 256>>>((float*)pkt, (float*)pv, (float*)pkv,
        CC, CC, SS, BS, BS, KVS, nullptr, nullptr, 0, 0);

    // 6. z
    compute_z<<<NB*SS/8, 256>>>((float*)pq, (float*)pksum, (float*)pz);

    // 7. enhanced = shortcut + z * (q @ kv)
    gemm_tc<2,false><<<dim3(CC/128, SS/128, NB), 256>>>((float*)pq, (float*)pkv, (float*)penh,
        SS, CC, CC, BS, KVS, BS, (float*)pz, (float*)psc, SS, BS);

    // 8. t = LN(enhanced)
    layernorm512<<<NB*SS, 128>>>((float*)penh, (float*)pt, lnm_g, lnm_b);

    // 9. a = t @ fc1_w + fc1_b   (32768 x 2048, K=512)
    gemm_tc<3,false><<<dim3(HD/128, (NB*SS)/128, 1), 256>>>((float*)pt, fc1_w, (float*)pa,
        NB*SS, HD, CC, 0, 0, 0, fc1_b, nullptr, 0, 0);

    // 10. ax = gelu(LN(dwconv3x3(a) + dw_b + a))
    dw_ln_gelu<<<NB*SS, 256>>>((float*)pa, dw_w, dw_b, ln1_g, ln1_b, (float*)pax);

    // 11. out = enhanced + ax @ fc2_w + fc2_b   (32768 x 512, K=2048)
    gemm_tc<4,false><<<dim3(CC/128, (NB*SS)/128, 1), 256>>>((float*)pax, fc2_w, out,
        NB*SS, CC, HD, 0, 0, 0, fc2_b, (float*)penh, 0, 0);
}

// round 4
// speedup vs baseline: 1.9141x; 1.1793x over previous
#include <cuda_runtime.h>
#include <cuda_bf16.h>
#include <math.h>
#include <stdint.h>

// Problem dims
#define NB 8
#define CC 512
#define SS 4096     // N = H*W tokens
#define HD 2048     // HID = 4*C
#define HH 64

// ---------------- scratch (device globals; no allocation allowed) ----------
__device__ float g_q  [(long long)NB*CC*SS];
__device__ float g_k  [(long long)NB*CC*SS];
__device__ float g_kt [(long long)NB*CC*SS];
__device__ float g_v  [(long long)NB*CC*SS];
__device__ float g_sc [(long long)NB*SS*CC];
__device__ float g_enh[(long long)NB*SS*CC];
__device__ float g_t  [(long long)NB*SS*CC];
__device__ float g_a  [(long long)NB*SS*HD];
__device__ float g_ax [(long long)NB*SS*HD];
__device__ float g_kv [(long long)NB*CC*CC];
__device__ float g_ksum[NB*CC];
__device__ float g_z  [NB*SS];

// ---------------- helpers ---------------------------------------------------
__device__ __forceinline__ float blockReduceSum(float val) {
    __shared__ float sh[32];
    int lane = threadIdx.x & 31, wid = threadIdx.x >> 5;
    #pragma unroll
    for (int o = 16; o > 0; o >>= 1) val += __shfl_xor_sync(0xffffffff, val, o);
    if (lane == 0) sh[wid] = val;
    __syncthreads();
    float tot = 0.f;
    if (wid == 0) {
        tot = (lane < (int)(blockDim.x >> 5)) ? sh[lane] : 0.f;
        #pragma unroll
        for (int o = 16; o > 0; o >>= 1) tot += __shfl_xor_sync(0xffffffff, tot, o);
        if (lane == 0) sh[0] = tot;
    }
    __syncthreads();
    tot = sh[0];
    __syncthreads();
    return tot;
}

__device__ __forceinline__ float blockReduceMax(float val) {
    __shared__ float sh[32];
    int lane = threadIdx.x & 31, wid = threadIdx.x >> 5;
    #pragma unroll
    for (int o = 16; o > 0; o >>= 1) val = fmaxf(val, __shfl_xor_sync(0xffffffff, val, o));
    if (lane == 0) sh[wid] = val;
    __syncthreads();
    float tot = -1e30f;
    if (wid == 0) {
        tot = (lane < (int)(blockDim.x >> 5)) ? sh[lane] : -1e30f;
        #pragma unroll
        for (int o = 16; o > 0; o >>= 1) tot = fmaxf(tot, __shfl_xor_sync(0xffffffff, tot, o));
        if (lane == 0) sh[0] = tot;
    }
    __syncthreads();
    tot = sh[0];
    __syncthreads();
    return tot;
}

__device__ __forceinline__ float cvt_tf32(float v) {
    uint32_t u;
    asm("cvt.rna.tf32.f32 %0, %1;" : "=r"(u) : "f"(v));
    return __uint_as_float(u);
}

__device__ __forceinline__ void cp16(uint32_t s, const void* g) {
    asm volatile("cp.async.cg.shared.global [%0], [%1], 16;" :: "r"(s), "l"(g));
}

#define MMA_TF32(d, a, b) \
    asm volatile("mma.sync.aligned.m16n8k8.row.col.f32.tf32.tf32.f32 " \
        "{%0,%1,%2,%3},{%4,%5,%6,%7},{%8,%9},{%0,%1,%2,%3};" \
        : "+f"(d[0]), "+f"(d[1]), "+f"(d[2]), "+f"(d[3]) \
        : "r"(a[0]), "r"(a[1]), "r"(a[2]), "r"(a[3]), "r"(b[0]), "r"(b[1]))

// ---------------- tensor-core TF32 GEMM, cp.async 2-stage pipeline ---------
// 128x128 tile, BK=16, 256 threads, warp tile 64x32 (2x4 warps).
// smem holds raw fp32; tf32 (and hi/lo split) conversion happens in registers
// after ldmatrix / LDS.
// MODE: 0 = +bias[row] (e0)
//       1 = plain
//       2 = acc*z[row] + shortcut[row*N+col]   (e0=z, e1=shortcut)
//       3 = +bias[col] (e0)
//       4 = +bias[col] + res[row*N+col]        (e0=bias, e1=res)
template<int MODE, bool SPLIT>
__global__ void __launch_bounds__(256)
gemm_tc(const float* __restrict__ A, const float* __restrict__ B,
        float* __restrict__ C, int M, int N, int K,
        long long strA, long long strB, long long strC,
        const float* __restrict__ e0, const float* __restrict__ e1,
        long long strE0, long long strE1)
{
    __shared__ float As[2][128][20];    // pad 20 floats/row (80B, 16B-aligned)
    __shared__ float Bs[2][16][136];

    const int bz = blockIdx.z;
    A += (long long)bz * strA;
    B += (long long)bz * strB;
    C += (long long)bz * strC;
    const float* E0 = e0 ? e0 + (long long)bz * strE0 : nullptr;
    const float* E1 = e1 ? e1 + (long long)bz * strE1 : nullptr;

    const int t    = threadIdx.x;
    const int lane = t & 31, warp = t >> 5;
    const int m0   = blockIdx.y * 128, n0 = blockIdx.x * 128;
    const int wm0  = (warp & 1) * 64;
    const int wn0  = (warp >> 1) * 32;

    // copy assignment
    const int arow = t >> 1,  acol = (t & 1) * 8;   // A: 2 x 16B per thread
    const int brow = t >> 4,  bcol = (t & 15) * 8;  // B: 2 x 16B per thread

    const uint32_t sA = (uint32_t)__cvta_generic_to_shared(&As[0][0][0]);
    const uint32_t sB = (uint32_t)__cvta_generic_to_shared(&Bs[0][0][0]);

    float acc[4][4][4];
    #pragma unroll
    for (int i = 0; i < 4; i++)
        #pragma unroll
        for (int j = 0; j < 4; j++)
            #pragma unroll
            for (int r = 0; r < 4; r++) acc[i][j][r] = 0.f;

    // fragment addressing
    const int aRow    = wm0 + (lane & 15);
    const int aColSel = (lane >> 4) << 2;
    const int bkRow   = lane & 3;
    const int bnCol   = wn0 + (lane >> 2);

    const int nk = K >> 4;

    // stage loader
    auto load_stage = [&](int kt, int buf) {
        const float* ap = A + (long long)(m0 + arow) * K + (kt << 4) + acol;
        uint32_t sa = sA + (uint32_t)((buf * 2560 + arow * 20 + acol) << 2);
        cp16(sa, ap);
        cp16(sa + 16, ap + 4);
        const float* bp = B + (long long)((kt << 4) + brow) * N + n0 + bcol;
        uint32_t sb = sB + (uint32_t)((buf * 2176 + brow * 136 + bcol) << 2);
        cp16(sb, bp);
        cp16(sb + 16, bp + 4);
    };

    load_stage(0, 0);
    asm volatile("cp.async.commit_group;" ::: "memory");

    for (int kt = 0; kt < nk; kt++) {
        asm volatile("cp.async.wait_group 0;" ::: "memory");
        __syncthreads();
        if (kt + 1 < nk) {
            load_stage(kt + 1, (kt + 1) & 1);
            asm volatile("cp.async.commit_group;" ::: "memory");
        }
        const int buf = kt & 1;

        #pragma unroll
        for (int k8 = 0; k8 < 16; k8 += 8) {
            // A fragments via ldmatrix on fp32-as-b16, then cvt in regs
            uint32_t ah[4][4], al[4][4];
            #pragma unroll
            for (int mt = 0; mt < 4; mt++) {
                uint32_t raw[4];
                uint32_t addr = sA +
                    ((uint32_t)(buf * 2560 + (aRow + mt * 16) * 20 + k8 + aColSel) << 2);
                asm volatile("ldmatrix.sync.aligned.m8n8.x4.shared.b16 {%0,%1,%2,%3}, [%4];"
                    : "=r"(raw[0]), "=r"(raw[1]), "=r"(raw[2]), "=r"(raw[3])
                    : "r"(addr) : "memory");
                #pragma unroll
                for (int r = 0; r < 4; r++) {
                    float f = __uint_as_float(raw[r]);
                    float h = cvt_tf32(f);
                    ah[mt][r] = __float_as_uint(h);
                    if (SPLIT) al[mt][r] = __float_as_uint(cvt_tf32(f - h));
                }
            }
            // B fragments via direct LDS, then cvt in regs
            uint32_t bh[4][2], bl[4][2];
            #pragma unroll
            for (int nt = 0; nt < 4; nt++) {
                #pragma unroll
                for (int j = 0; j < 2; j++) {
                    float f = Bs[buf][k8 + bkRow + j * 4][bnCol + nt * 8];
                    float h = cvt_tf32(f);
                    bh[nt][j] = __float_as_uint(h);
                    if (SPLIT) bl[nt][j] = __float_as_uint(cvt_tf32(f - h));
                }
            }
            #pragma unroll
            for (int mt = 0; mt < 4; mt++)
                #pragma unroll
                for (int nt = 0; nt < 4; nt++) {
                    MMA_TF32(acc[mt][nt], ah[mt], bh[nt]);
                    if (SPLIT) {
                        MMA_TF32(acc[mt][nt], ah[mt], bl[nt]);
                        MMA_TF32(acc[mt][nt], al[mt], bh[nt]);
                    }
                }
        }
        __syncthreads();
    }

    // ---- epilogue ----
    #pragma unroll
    for (int mt = 0; mt < 4; mt++) {
        #pragma unroll
        for (int half = 0; half < 2; half++) {
            int r = m0 + wm0 + mt * 16 + (lane >> 2) + half * 8;
            #pragma unroll
            for (int nt = 0; nt < 4; nt++) {
                int c = n0 + wn0 + nt * 8 + (lane & 3) * 2;
                float v0 = acc[mt][nt][half * 2 + 0];
                float v1 = acc[mt][nt][half * 2 + 1];
                long long off = (long long)r * N + c;
                if (MODE == 0) { float b = E0[r]; v0 += b; v1 += b; }
                if (MODE == 2) {
                    float zz = E0[r];
                    float2 s = *reinterpret_cast<const float2*>(&E1[off]);
                    v0 = v0 * zz + s.x; v1 = v1 * zz + s.y;
                }
                if (MODE == 3) { v0 += E0[c]; v1 += E0[c + 1]; }
                if (MODE == 4) {
                    float2 s = *reinterpret_cast<const float2*>(&E1[off]);
                    v0 += E0[c] + s.x; v1 += E0[c + 1] + s.y;
                }
                *reinterpret_cast<float2*>(&C[off]) = make_float2(v0, v1);
            }
        }
    }
}

// ---------------- transpose x (B,C,S) -> (B,S,C) ---------------------------
__global__ void transpose_x(const float* __restrict__ x, float* __restrict__ out)
{
    __shared__ float tile[32][33];
    int b  = blockIdx.z;
    int s0 = blockIdx.x * 32, c0 = blockIdx.y * 32;
    const float* xb = x   + (long long)b * CC * SS;
    float*       ob = out + (long long)b * SS * CC;
    int txx = threadIdx.x, tyy = threadIdx.y; // (32, 8)
    #pragma unroll
    for (int i = 0; i < 32; i += 8)
        tile[tyy + i][txx] = xb[(long long)(c0 + tyy + i) * SS + s0 + txx];
    __syncthreads();
    #pragma unroll
    for (int i = 0; i < 32; i += 8)
        ob[(long long)(s0 + tyy + i) * CC + c0 + txx] = tile[txx][tyy + i];
}

// ---------------- transpose (B,S,C) -> (B,C,S)  (for kT) -------------------
__global__ void transpose_sc(const float* __restrict__ in, float* __restrict__ out)
{
    __shared__ float tile[32][33];
    int b  = blockIdx.z;
    int s0 = blockIdx.x * 32, c0 = blockIdx.y * 32;
    const float* ib = in  + (long long)b * SS * CC;
    float*       ob = out + (long long)b * CC * SS;
    int txx = threadIdx.x, tyy = threadIdx.y; // (32, 8)
    #pragma unroll
    for (int i = 0; i < 32; i += 8)
        tile[tyy + i][txx] = ib[(long long)(s0 + tyy + i) * CC + c0 + txx];
    __syncthreads();
    #pragma unroll
    for (int i = 0; i < 32; i += 8)
        ob[(long long)(c0 + tyy + i) * SS + s0 + txx] = tile[txx][tyy + i];
}

// ---------------- q: softmax over tokens (axis=1, strided columns) ---------
__global__ void softmax_col_q(float* __restrict__ q, const float* __restrict__ scale)
{
    int b   = blockIdx.y;
    int col = blockIdx.x * 32 + threadIdx.x;
    int ry  = threadIdx.y;
    float* base = q + (long long)b * SS * CC + col;

    float m = -1e30f, s = 0.f;
    int i0 = ry * 256;
    for (int i = i0; i < i0 + 256; ++i) {
        float v  = base[(long long)i * CC];
        float mn = fmaxf(m, v);
        s = s * __expf(m - mn) + __expf(v - mn);
        m = mn;
    }
    __shared__ float sm[16][32], ss[16][32];
    sm[ry][threadIdx.x] = m; ss[ry][threadIdx.x] = s;
    __syncthreads();
    if (ry == 0) {
        float M = sm[0][threadIdx.x], S = ss[0][threadIdx.x];
        for (int r2 = 1; r2 < 16; r2++) {
            float m2 = sm[r2][threadIdx.x], s2 = ss[r2][threadIdx.x];
            float mn = fmaxf(M, m2);
            S = S * __expf(M - mn) + s2 * __expf(m2 - mn);
            M = mn;
        }
        sm[0][threadIdx.x] = M; ss[0][threadIdx.x] = S;
    }
    __syncthreads();
    float M   = sm[0][threadIdx.x];
    float inv = 1.f / ss[0][threadIdx.x];
    float isc = 1.f / log1pf(__expf(scale[col]));
    for (int i = i0; i < i0 + 256; ++i) {
        float v = base[(long long)i * CC];
        base[(long long)i * CC] = (__expf(v - M) * inv + 1e-6f) * isc;
    }
}

// ---------------- q row renorm: q = q^3 / ||q^3|| * ||q|| -------------------
__global__ void rownorm_pow3(float* __restrict__ buf)
{
    long long row = blockIdx.x;
    float* p = buf + row * CC;
    int t = threadIdx.x; // 128
    float4 f4 = *reinterpret_cast<const float4*>(p + t * 4);
    float v[4] = { f4.x, f4.y, f4.z, f4.w };
    float s1 = 0.f;
    #pragma unroll
    for (int r = 0; r < 4; r++) s1 += v[r] * v[r];
    s1 = blockReduceSum(s1);
    float u3[4];
    float s3 = 0.f;
    #pragma unroll
    for (int r = 0; r < 4; r++) { u3[r] = v[r] * v[r] * v[r]; s3 += u3[r] * u3[r]; }
    s3 = blockReduceSum(s3);
    float f = sqrtf(s1) / sqrtf(s3);
    float4 o = make_float4(u3[0] * f, u3[1] * f, u3[2] * f, u3[3] * f);
    *reinterpret_cast<float4*>(p + t * 4) = o;
}

// ---------------- k: row softmax + transform + renorm + ksum ---------------
__global__ void softmax_row_k(float* __restrict__ kbuf, const float* __restrict__ scale,
                              float* __restrict__ ksum)
{
    long long row = blockIdx.x;          // b*SS + i
    int b = (int)(row >> 12);
    float* p = kbuf + row * CC;
    int t = threadIdx.x; // 128
    float4 f4 = *reinterpret_cast<const float4*>(p + t * 4);
    float v[4] = { f4.x, f4.y, f4.z, f4.w };
    float mx = fmaxf(fmaxf(v[0], v[1]), fmaxf(v[2], v[3]));
    mx = blockReduceMax(mx);
    float se = 0.f;
    #pragma unroll
    for (int r = 0; r < 4; r++) se += __expf(v[r] - mx);
    se = blockReduceSum(se);
    float inv = 1.f / se;
    float u[4];
    #pragma unroll
    for (int r = 0; r < 4; r++) {
        float isc = 1.f / log1pf(__expf(scale[t * 4 + r]));
        u[r] = (__expf(v[r] - mx) * inv + 1e-6f) * isc;
    }
    float s1 = 0.f;
    #pragma unroll
    for (int r = 0; r < 4; r++) s1 += u[r] * u[r];
    s1 = blockReduceSum(s1);
    float u3[4];
    float s3 = 0.f;
    #pragma unroll
    for (int r = 0; r < 4; r++) { u3[r] = u[r] * u[r] * u[r]; s3 += u3[r] * u3[r]; }
    s3 = blockReduceSum(s3);
    float f = sqrtf(s1) / sqrtf(s3);
    float o[4];
    #pragma unroll
    for (int r = 0; r < 4; r++) o[r] = u3[r] * f;
    *reinterpret_cast<float4*>(p + t * 4) = make_float4(o[0], o[1], o[2], o[3]);
    #pragma unroll
    for (int r = 0; r < 4; r++)
        atomicAdd(&ksum[b * CC + t * 4 + r], o[r]);
}

__global__ void zero_ksum(float* __restrict__ ksum)
{
    int i = blockIdx.x * blockDim.x + threadIdx.x;
    if (i < NB * CC) ksum[i] = 0.f;
}

// ---------------- z[b,i] = 1/(q_row . ksum_b + 1e-6) ------------------------
__global__ void compute_z(const float* __restrict__ q, const float* __restrict__ ksum,
                          float* __restrict__ z)
{
    long long row = (long long)blockIdx.x * 8 + (threadIdx.x >> 5);
    int lane = threadIdx.x & 31;
    int b = (int)(row >> 12);
    const float* p  = q + row * CC;
    const float* ks = ksum + b * CC;
    float s = 0.f;
    for (int c = lane; c < CC; c += 32) s += p[c] * ks[c];
    #pragma unroll
    for (int o = 16; o > 0; o >>= 1) s += __shfl_xor_sync(0xffffffff, s, o);
    if (lane == 0) z[row] = 1.f / (s + 1e-6f);
}

// ---------------- LayerNorm over C=512 --------------------------------------
__global__ void layernorm512(const float* __restrict__ in, float* __restrict__ out,
                             const float* __restrict__ g, const float* __restrict__ bta)
{
    long long row = blockIdx.x;
    const float* p = in + row * CC;
    int t = threadIdx.x; // 128
    float4 f4 = *reinterpret_cast<const float4*>(p + t * 4);
    float v[4] = { f4.x, f4.y, f4.z, f4.w };
    float s = v[0] + v[1] + v[2] + v[3];
    s = blockReduceSum(s);
    float mean = s * (1.f / (float)CC);
    float s2 = 0.f;
    #pragma unroll
    for (int r = 0; r < 4; r++) { float d = v[r] - mean; s2 += d * d; }
    s2 = blockReduceSum(s2);
    float rstd = rsqrtf(s2 * (1.f / (float)CC) + 1e-5f);
    float o[4];
    #pragma unroll
    for (int r = 0; r < 4; r++) {
        int c = t * 4 + r;
        o[r] = (v[r] - mean) * rstd * g[c] + bta[c];
    }
    *reinterpret_cast<float4*>(out + row * CC + t * 4) = make_float4(o[0], o[1], o[2], o[3]);
}

// ---------------- depthwise 3x3 + residual + LN(HID) + exact GELU ----------
__global__ void dw_ln_gelu(const float* __restrict__ a, const float* __restrict__ w,
                           const float* __restrict__ wb, const float* __restrict__ g,
                           const float* __restrict__ beta, float* __restrict__ out)
{
    long long idx = blockIdx.x;          // b*SS + s
    int b = (int)(idx >> 12);
    int s = (int)(idx & 4095);
    int y = s >> 6, x = s & 63;
    int t = threadIdx.x;                 // 256, each handles 8 channels
    const float* ab = a + (long long)b * SS * HD;

    float val[8];
    float sum = 0.f;
    #pragma unroll
    for (int r = 0; r < 8; r++) {
        int h = r * 256 + t;
        float acc = wb[h];
        #pragma unroll
        for (int ky = 0; ky < 3; ky++) {
            int yy = y + ky - 1;
            if (yy < 0 || yy > 63) continue;
            #pragma unroll
            for (int kx = 0; kx < 3; kx++) {
                int xx = x + kx - 1;
                if (xx < 0 || xx > 63) continue;
                acc += w[h * 9 + ky * 3 + kx] * ab[((long long)(yy * 64 + xx)) * HD + h];
            }
        }
        acc += ab[(long long)s * HD + h];      // + a (skip before LN)
        val[r] = acc;
        sum += acc;
    }
    sum = blockReduceSum(sum);
    float mean = sum * (1.f / (float)HD);
    float s2 = 0.f;
    #pragma unroll
    for (int r = 0; r < 8; r++) { float d = val[r] - mean; s2 += d * d; }
    s2 = blockReduceSum(s2);
    float rstd = rsqrtf(s2 * (1.f / (float)HD) + 1e-5f);
    #pragma unroll
    for (int r = 0; r < 8; r++) {
        int h = r * 256 + t;
        float yv = (val[r] - mean) * rstd * g[h] + beta[h];
        float ge = 0.5f * yv * (1.f + erff(yv * 0.70710678118654752f));
        out[idx * HD + h] = ge;
    }
}

// ---------------- launch ----------------------------------------------------
extern "C" void kernel_launch(void* const* d_in, const int* in_sizes, int n_in,
                              void* d_out, int out_size)
{
    const float* x      = (const float*)d_in[0];
    const float* Wq     = (const float*)d_in[1];
    const float* bq     = (const float*)d_in[2];
    const float* Wk     = (const float*)d_in[3];
    const float* bk     = (const float*)d_in[4];
    const float* Wv     = (const float*)d_in[5];
    const float* bv     = (const float*)d_in[6];
    const float* scale  = (const float*)d_in[7];
    const float* fc1_w  = (const float*)d_in[8];
    const float* fc1_b  = (const float*)d_in[9];
    const float* dw_w   = (const float*)d_in[10];
    const float* dw_b   = (const float*)d_in[11];
    const float* fc2_w  = (const float*)d_in[12];
    const float* fc2_b  = (const float*)d_in[13];
    const float* ln1_g  = (const float*)d_in[14];
    const float* ln1_b  = (const float*)d_in[15];
    const float* lnm_g  = (const float*)d_in[16];
    const float* lnm_b  = (const float*)d_in[17];
    float* out = (float*)d_out;

    void *pq, *pk, *pkt, *pv, *psc, *penh, *pt, *pa, *pax, *pkv, *pksum, *pz;
    cudaGetSymbolAddress(&pq,   g_q);
    cudaGetSymbolAddress(&pk,   g_k);
    cudaGetSymbolAddress(&pkt,  g_kt);
    cudaGetSymbolAddress(&pv,   g_v);
    cudaGetSymbolAddress(&psc,  g_sc);
    cudaGetSymbolAddress(&penh, g_enh);
    cudaGetSymbolAddress(&pt,   g_t);
    cudaGetSymbolAddress(&pa,   g_a);
    cudaGetSymbolAddress(&pax,  g_ax);
    cudaGetSymbolAddress(&pkv,  g_kv);
    cudaGetSymbolAddress(&pksum,g_ksum);
    cudaGetSymbolAddress(&pz,   g_z);

    const long long BS  = (long long)CC * SS;
    const long long KVS = (long long)CC * CC;

    // 1. shortcut = x^T per batch
    transpose_x<<<dim3(SS/32, CC/32, NB), dim3(32, 8)>>>(x, (float*)psc);

    // 2. qkv GEMMs: q,k split-tf32; v single-tf32
    gemm_tc<0,true ><<<dim3(SS/128, CC/128, NB), 256>>>(Wq, x, (float*)pq, CC, SS, CC,
        0, BS, BS, bq, nullptr, 0, 0);
    gemm_tc<0,true ><<<dim3(SS/128, CC/128, NB), 256>>>(Wk, x, (float*)pk, CC, SS, CC,
        0, BS, BS, bk, nullptr, 0, 0);
    gemm_tc<0,false><<<dim3(SS/128, CC/128, NB), 256>>>(Wv, x, (float*)pv, CC, SS, CC,
        0, BS, BS, bv, nullptr, 0, 0);

    // 3. q path: column softmax, then row renorm^3
    softmax_col_q<<<dim3(CC/32, NB), dim3(32, 16)>>>((float*)pq, scale);
    rownorm_pow3<<<NB*SS, 128>>>((float*)pq);

    // 4. k path: row softmax + transform + renorm + ksum
    zero_ksum<<<4, 1024>>>((float*)pksum);
    softmax_row_k<<<NB*SS, 128>>>((float*)pk, scale, (float*)pksum);

    // 4b. kT = transpose(k): (S,C) -> (C,S)
    transpose_sc<<<dim3(SS/32, CC/32, NB), dim3(32, 8)>>>((float*)pk, (float*)pkt);

    // 5. kv = kT @ v  (512x512, K=4096)
    gemm_tc<1,false><<<dim3(CC/128, CC/128, NB), 256>>>((float*)pkt, (float*)pv, (float*)pkv,
        CC, CC, SS, BS, BS, KVS, nullptr, nullptr, 0, 0);

    // 6. z
    compute_z<<<NB*SS/8, 256>>>((float*)pq, (float*)pksum, (float*)pz);

    // 7. enhanced = shortcut + z * (q @ kv)
    gemm_tc<2,false><<<dim3(CC/128, SS/128, NB), 256>>>((float*)pq, (float*)pkv, (float*)penh,
        SS, CC, CC, BS, KVS, BS, (float*)pz, (float*)psc, SS, BS);

    // 8. t = LN(enhanced)
    layernorm512<<<NB*SS, 128>>>((float*)penh, (float*)pt, lnm_g, lnm_b);

    // 9. a = t @ fc1_w + fc1_b   (32768 x 2048, K=512)
    gemm_tc<3,false><<<dim3(HD/128, (NB*SS)/128, 1), 256>>>((float*)pt, fc1_w, (float*)pa,
        NB*SS, HD, CC, 0, 0, 0, fc1_b, nullptr, 0, 0);

    // 10. ax = gelu(LN(dwconv3x3(a) + dw_b + a))
    dw_ln_gelu<<<NB*SS, 256>>>((float*)pa, dw_w, dw_b, ln1_g, ln1_b, (float*)pax);

    // 11. out = enhanced + ax @ fc2_w + fc2_b   (32768 x 512, K=2048)
    gemm_tc<4,false><<<dim3(CC/128, (NB*SS)/128, 1), 256>>>((float*)pax, fc2_w, out,
        NB*SS, CC, HD, 0, 0, 0, fc2_b, (float*)penh, 0, 0);
}

// round 5
// speedup vs baseline: 2.0605x; 1.0765x over previous
#include <cuda_runtime.h>
#include <cuda_bf16.h>
#include <math.h>
#include <stdint.h>

// Problem dims
#define NB 8
#define CC 512
#define SS 4096     // N = H*W tokens
#define HD 2048     // HID = 4*C
#define HH 64

#define STAGES 4

// ---------------- scratch (device globals; no allocation allowed) ----------
__device__ float g_q  [(long long)NB*CC*SS];
__device__ float g_k  [(long long)NB*CC*SS];
__device__ float g_kt [(long long)NB*CC*SS];
__device__ float g_v  [(long long)NB*CC*SS];
__device__ float g_sc [(long long)NB*SS*CC];
__device__ float g_enh[(long long)NB*SS*CC];
__device__ float g_t  [(long long)NB*SS*CC];
__device__ float g_a  [(long long)NB*SS*HD];
__device__ float g_ax [(long long)NB*SS*HD];
__device__ float g_kv [(long long)NB*CC*CC];
__device__ float g_w1 [(long long)CC*HD];     // tf32-rounded fc1_w
__device__ float g_w2 [(long long)HD*CC];     // tf32-rounded fc2_w
__device__ float g_ksum[NB*CC];
__device__ float g_z  [NB*SS];

// ---------------- helpers ---------------------------------------------------
__device__ __forceinline__ float blockReduceSum(float val) {
    __shared__ float sh[32];
    int lane = threadIdx.x & 31, wid = threadIdx.x >> 5;
    #pragma unroll
    for (int o = 16; o > 0; o >>= 1) val += __shfl_xor_sync(0xffffffff, val, o);
    if (lane == 0) sh[wid] = val;
    __syncthreads();
    float tot = 0.f;
    if (wid == 0) {
        tot = (lane < (int)(blockDim.x >> 5)) ? sh[lane] : 0.f;
        #pragma unroll
        for (int o = 16; o > 0; o >>= 1) tot += __shfl_xor_sync(0xffffffff, tot, o);
        if (lane == 0) sh[0] = tot;
    }
    __syncthreads();
    tot = sh[0];
    __syncthreads();
    return tot;
}

__device__ __forceinline__ float blockReduceMax(float val) {
    __shared__ float sh[32];
    int lane = threadIdx.x & 31, wid = threadIdx.x >> 5;
    #pragma unroll
    for (int o = 16; o > 0; o >>= 1) val = fmaxf(val, __shfl_xor_sync(0xffffffff, val, o));
    if (lane == 0) sh[wid] = val;
    __syncthreads();
    float tot = -1e30f;
    if (wid == 0) {
        tot = (lane < (int)(blockDim.x >> 5)) ? sh[lane] : -1e30f;
        #pragma unroll
        for (int o = 16; o > 0; o >>= 1) tot = fmaxf(tot, __shfl_xor_sync(0xffffffff, tot, o));
        if (lane == 0) sh[0] = tot;
    }
    __syncthreads();
    tot = sh[0];
    __syncthreads();
    return tot;
}

__device__ __forceinline__ float cvt_tf32(float v) {
    uint32_t u;
    asm("cvt.rna.tf32.f32 %0, %1;" : "=r"(u) : "f"(v));
    return __uint_as_float(u);
}

__device__ __forceinline__ void cp16(uint32_t s, const void* g) {
    asm volatile("cp.async.cg.shared.global [%0], [%1], 16;" :: "r"(s), "l"(g));
}

#define MMA_TF32(d, a, b) \
    asm volatile("mma.sync.aligned.m16n8k8.row.col.f32.tf32.tf32.f32 " \
        "{%0,%1,%2,%3},{%4,%5,%6,%7},{%8,%9},{%0,%1,%2,%3};" \
        : "+f"(d[0]), "+f"(d[1]), "+f"(d[2]), "+f"(d[3]) \
        : "r"(a[0]), "r"(a[1]), "r"(a[2]), "r"(a[3]), "r"(b[0]), "r"(b[1]))

// smem layout (dynamic): As [STAGES][128][20], Bs [STAGES][16][136]
#define AS_FLOATS (STAGES * 128 * 20)
#define BS_FLOATS (STAGES * 16 * 136)
#define SMEM_GEMM_BYTES ((AS_FLOATS + BS_FLOATS) * 4)

// ---------------- tensor-core TF32 GEMM, cp.async 4-stage pipeline ---------
// 128x128 tile, BK=16, 256 threads, warp tile 64x32 (2x4 warps).
// MODE: 0 = +bias[row] (e0)
//       1 = plain
//       2 = acc*z[row] + shortcut[row*N+col]   (e0=z, e1=shortcut)
//       3 = +bias[col] (e0)
//       4 = +bias[col] + res[row*N+col]        (e0=bias, e1=res)
// SPLIT: 3xTF32 hi/lo in registers.  CVT: convert fragments (else raw bits,
// valid when inputs are pre-rounded to tf32).  RND: round stores to tf32.
template<int MODE, bool SPLIT, bool CVT, bool RND>
__global__ void __launch_bounds__(256, 2)
gemm_tc(const float* __restrict__ A, const float* __restrict__ B,
        float* __restrict__ C, int M, int N, int K,
        long long strA, long long strB, long long strC,
        const float* __restrict__ e0, const float* __restrict__ e1,
        long long strE0, long long strE1)
{
    extern __shared__ float smem[];
    float* Asm = smem;                 // [s][m][c] -> (s*128+m)*20 + c
    float* Bsm = smem + AS_FLOATS;     // [s][k][n] -> (s*16+k)*136 + n

    const int bz = blockIdx.z;
    A += (long long)bz * strA;
    B += (long long)bz * strB;
    C += (long long)bz * strC;
    const float* E0 = e0 ? e0 + (long long)bz * strE0 : nullptr;
    const float* E1 = e1 ? e1 + (long long)bz * strE1 : nullptr;

    const int t    = threadIdx.x;
    const int lane = t & 31, warp = t >> 5;
    const int m0   = blockIdx.y * 128, n0 = blockIdx.x * 128;
    const int wm0  = (warp & 1) * 64;
    const int wn0  = (warp >> 1) * 32;

    // copy assignment
    const int arow = t >> 1,  acol = (t & 1) * 8;   // A: 2 x 16B per thread
    const int brow = t >> 4,  bcol = (t & 15) * 8;  // B: 2 x 16B per thread

    const uint32_t sA = (uint32_t)__cvta_generic_to_shared(Asm);
    const uint32_t sB = (uint32_t)__cvta_generic_to_shared(Bsm);

    float acc[4][4][4];
    #pragma unroll
    for (int i = 0; i < 4; i++)
        #pragma unroll
        for (int j = 0; j < 4; j++)
            #pragma unroll
            for (int r = 0; r < 4; r++) acc[i][j][r] = 0.f;

    // fragment addressing
    const int aRow    = wm0 + (lane & 15);
    const int aColSel = (lane >> 4) << 2;
    const int bkRow   = lane & 3;
    const int bnCol   = wn0 + (lane >> 2);

    const int nk = K >> 4;

    auto load_stage = [&](int kt, int buf) {
        const float* ap = A + (long long)(m0 + arow) * K + (kt << 4) + acol;
        uint32_t sa = sA + (uint32_t)(((buf * 128 + arow) * 20 + acol) << 2);
        cp16(sa, ap);
        cp16(sa + 16, ap + 4);
        const float* bp = B + (long long)((kt << 4) + brow) * N + n0 + bcol;
        uint32_t sb = sB + (uint32_t)(((buf * 16 + brow) * 136 + bcol) << 2);
        cp16(sb, bp);
        cp16(sb + 16, bp + 4);
    };

    #pragma unroll
    for (int s = 0; s < STAGES - 1; s++) {
        load_stage(s, s);
        asm volatile("cp.async.commit_group;" ::: "memory");
    }

    for (int kt = 0; kt < nk; kt++) {
        asm volatile("cp.async.wait_group %0;" :: "n"(STAGES - 2) : "memory");
        __syncthreads();
        {
            int pf = kt + STAGES - 1;
            if (pf < nk) load_stage(pf, pf & (STAGES - 1));
            asm volatile("cp.async.commit_group;" ::: "memory");
        }
        const int buf = kt & (STAGES - 1);

        #pragma unroll
        for (int k8 = 0; k8 < 16; k8 += 8) {
            uint32_t ah[4][4], al[4][4];
            #pragma unroll
            for (int mt = 0; mt < 4; mt++) {
                uint32_t raw[4];
                uint32_t addr = sA +
                    ((uint32_t)(((buf * 128 + aRow + mt * 16) * 20) + k8 + aColSel) << 2);
                asm volatile("ldmatrix.sync.aligned.m8n8.x4.shared.b16 {%0,%1,%2,%3}, [%4];"
                    : "=r"(raw[0]), "=r"(raw[1]), "=r"(raw[2]), "=r"(raw[3])
                    : "r"(addr) : "memory");
                #pragma unroll
                for (int r = 0; r < 4; r++) {
                    if (CVT) {
                        float f = __uint_as_float(raw[r]);
                        float h = cvt_tf32(f);
                        ah[mt][r] = __float_as_uint(h);
                        if (SPLIT) al[mt][r] = __float_as_uint(cvt_tf32(f - h));
                    } else {
                        ah[mt][r] = raw[r];
                    }
                }
            }
            uint32_t bh[4][2], bl[4][2];
            #pragma unroll
            for (int nt = 0; nt < 4; nt++) {
                #pragma unroll
                for (int j = 0; j < 2; j++) {
                    float f = Bsm[(buf * 16 + k8 + bkRow + j * 4) * 136 + bnCol + nt * 8];
                    if (CVT) {
                        float h = cvt_tf32(f);
                        bh[nt][j] = __float_as_uint(h);
                        if (SPLIT) bl[nt][j] = __float_as_uint(cvt_tf32(f - h));
                    } else {
                        bh[nt][j] = __float_as_uint(f);
                    }
                }
            }
            #pragma unroll
            for (int mt = 0; mt < 4; mt++)
                #pragma unroll
                for (int nt = 0; nt < 4; nt++) {
                    MMA_TF32(acc[mt][nt], ah[mt], bh[nt]);
                    if (SPLIT) {
                        MMA_TF32(acc[mt][nt], ah[mt], bl[nt]);
                        MMA_TF32(acc[mt][nt], al[mt], bh[nt]);
                    }
                }
        }
    }

    // ---- epilogue ----
    #pragma unroll
    for (int mt = 0; mt < 4; mt++) {
        #pragma unroll
        for (int half = 0; half < 2; half++) {
            int r = m0 + wm0 + mt * 16 + (lane >> 2) + half * 8;
            #pragma unroll
            for (int nt = 0; nt < 4; nt++) {
                int c = n0 + wn0 + nt * 8 + (lane & 3) * 2;
                float v0 = acc[mt][nt][half * 2 + 0];
                float v1 = acc[mt][nt][half * 2 + 1];
                long long off = (long long)r * N + c;
                if (MODE == 0) { float b = E0[r]; v0 += b; v1 += b; }
                if (MODE == 2) {
                    float zz = E0[r];
                    float2 s = *reinterpret_cast<const float2*>(&E1[off]);
                    v0 = v0 * zz + s.x; v1 = v1 * zz + s.y;
                }
                if (MODE == 3) { v0 += E0[c]; v1 += E0[c + 1]; }
                if (MODE == 4) {
                    float2 s = *reinterpret_cast<const float2*>(&E1[off]);
                    v0 += E0[c] + s.x; v1 += E0[c + 1] + s.y;
                }
                if (RND) { v0 = cvt_tf32(v0); v1 = cvt_tf32(v1); }
                *reinterpret_cast<float2*>(&C[off]) = make_float2(v0, v1);
            }
        }
    }
}

// ---------------- elementwise tf32 rounding (for weights) ------------------
__global__ void round_tf32_kernel(const float* __restrict__ in, float* __restrict__ out, int n4)
{
    int i = blockIdx.x * blockDim.x + threadIdx.x;
    if (i < n4) {
        float4 v = reinterpret_cast<const float4*>(in)[i];
        v.x = cvt_tf32(v.x); v.y = cvt_tf32(v.y);
        v.z = cvt_tf32(v.z); v.w = cvt_tf32(v.w);
        reinterpret_cast<float4*>(out)[i] = v;
    }
}

// ---------------- transpose x (B,C,S) -> (B,S,C) ---------------------------
__global__ void transpose_x(const float* __restrict__ x, float* __restrict__ out)
{
    __shared__ float tile[32][33];
    int b  = blockIdx.z;
    int s0 = blockIdx.x * 32, c0 = blockIdx.y * 32;
    const float* xb = x   + (long long)b * CC * SS;
    float*       ob = out + (long long)b * SS * CC;
    int txx = threadIdx.x, tyy = threadIdx.y; // (32, 8)
    #pragma unroll
    for (int i = 0; i < 32; i += 8)
        tile[tyy + i][txx] = xb[(long long)(c0 + tyy + i) * SS + s0 + txx];
    __syncthreads();
    #pragma unroll
    for (int i = 0; i < 32; i += 8)
        ob[(long long)(s0 + tyy + i) * CC + c0 + txx] = tile[txx][tyy + i];
}

// ---------------- transpose (B,S,C) -> (B,C,S)  (for kT) -------------------
__global__ void transpose_sc(const float* __restrict__ in, float* __restrict__ out)
{
    __shared__ float tile[32][33];
    int b  = blockIdx.z;
    int s0 = blockIdx.x * 32, c0 = blockIdx.y * 32;
    const float* ib = in  + (long long)b * SS * CC;
    float*       ob = out + (long long)b * CC * SS;
    int txx = threadIdx.x, tyy = threadIdx.y; // (32, 8)
    #pragma unroll
    for (int i = 0; i < 32; i += 8)
        tile[tyy + i][txx] = ib[(long long)(s0 + tyy + i) * CC + c0 + txx];
    __syncthreads();
    #pragma unroll
    for (int i = 0; i < 32; i += 8)
        ob[(long long)(c0 + tyy + i) * SS + s0 + txx] = tile[txx][tyy + i];
}

// ---------------- q: softmax over tokens (axis=1, strided columns) ---------
__global__ void softmax_col_q(float* __restrict__ q, const float* __restrict__ scale)
{
    int b   = blockIdx.y;
    int col = blockIdx.x * 32 + threadIdx.x;
    int ry  = threadIdx.y;
    float* base = q + (long long)b * SS * CC + col;

    float m = -1e30f, s = 0.f;
    int i0 = ry * 256;
    for (int i = i0; i < i0 + 256; ++i) {
        float v  = base[(long long)i * CC];
        float mn = fmaxf(m, v);
        s = s * __expf(m - mn) + __expf(v - mn);
        m = mn;
    }
    __shared__ float sm[16][32], ss[16][32];
    sm[ry][threadIdx.x] = m; ss[ry][threadIdx.x] = s;
    __syncthreads();
    if (ry == 0) {
        float M = sm[0][threadIdx.x], S = ss[0][threadIdx.x];
        for (int r2 = 1; r2 < 16; r2++) {
            float m2 = sm[r2][threadIdx.x], s2 = ss[r2][threadIdx.x];
            float mn = fmaxf(M, m2);
            S = S * __expf(M - mn) + s2 * __expf(m2 - mn);
            M = mn;
        }
        sm[0][threadIdx.x] = M; ss[0][threadIdx.x] = S;
    }
    __syncthreads();
    float M   = sm[0][threadIdx.x];
    float inv = 1.f / ss[0][threadIdx.x];
    float isc = 1.f / log1pf(__expf(scale[col]));
    for (int i = i0; i < i0 + 256; ++i) {
        float v = base[(long long)i * CC];
        base[(long long)i * CC] = (__expf(v - M) * inv + 1e-6f) * isc;
    }
}

// ---------------- q row renorm: q = q^3 / ||q^3|| * ||q||, tf32-rounded ----
__global__ void rownorm_pow3(float* __restrict__ buf)
{
    long long row = blockIdx.x;
    float* p = buf + row * CC;
    int t = threadIdx.x; // 128
    float4 f4 = *reinterpret_cast<const float4*>(p + t * 4);
    float v[4] = { f4.x, f4.y, f4.z, f4.w };
    float s1 = 0.f;
    #pragma unroll
    for (int r = 0; r < 4; r++) s1 += v[r] * v[r];
    s1 = blockReduceSum(s1);
    float u3[4];
    float s3 = 0.f;
    #pragma unroll
    for (int r = 0; r < 4; r++) { u3[r] = v[r] * v[r] * v[r]; s3 += u3[r] * u3[r]; }
    s3 = blockReduceSum(s3);
    float f = sqrtf(s1) / sqrtf(s3);
    float4 o = make_float4(cvt_tf32(u3[0] * f), cvt_tf32(u3[1] * f),
                           cvt_tf32(u3[2] * f), cvt_tf32(u3[3] * f));
    *reinterpret_cast<float4*>(p + t * 4) = o;
}

// ---------------- k: row softmax + transform + renorm + ksum (tf32) --------
__global__ void softmax_row_k(float* __restrict__ kbuf, const float* __restrict__ scale,
                              float* __restrict__ ksum)
{
    long long row = blockIdx.x;          // b*SS + i
    int b = (int)(row >> 12);
    float* p = kbuf + row * CC;
    int t = threadIdx.x; // 128
    float4 f4 = *reinterpret_cast<const float4*>(p + t * 4);
    float v[4] = { f4.x, f4.y, f4.z, f4.w };
    float mx = fmaxf(fmaxf(v[0], v[1]), fmaxf(v[2], v[3]));
    mx = blockReduceMax(mx);
    float se = 0.f;
    #pragma unroll
    for (int r = 0; r < 4; r++) se += __expf(v[r] - mx);
    se = blockReduceSum(se);
    float inv = 1.f / se;
    float u[4];
    #pragma unroll
    for (int r = 0; r < 4; r++) {
        float isc = 1.f / log1pf(__expf(scale[t * 4 + r]));
        u[r] = (__expf(v[r] - mx) * inv + 1e-6f) * isc;
    }
    float s1 = 0.f;
    #pragma unroll
    for (int r = 0; r < 4; r++) s1 += u[r] * u[r];
    s1 = blockReduceSum(s1);
    float u3[4];
    float s3 = 0.f;
    #pragma unroll
    for (int r = 0; r < 4; r++) { u3[r] = u[r] * u[r] * u[r]; s3 += u3[r] * u3[r]; }
    s3 = blockReduceSum(s3);
    float f = sqrtf(s1) / sqrtf(s3);
    float o[4];
    #pragma unroll
    for (int r = 0; r < 4; r++) o[r] = cvt_tf32(u3[r] * f);
    *reinterpret_cast<float4*>(p + t * 4) = make_float4(o[0], o[1], o[2], o[3]);
    #pragma unroll
    for (int r = 0; r < 4; r++)
        atomicAdd(&ksum[b * CC + t * 4 + r], o[r]);
}

__global__ void zero_ksum(float* __restrict__ ksum)
{
    int i = blockIdx.x * blockDim.x + threadIdx.x;
    if (i < NB * CC) ksum[i] = 0.f;
}

// ---------------- z[b,i] = 1/(q_row . ksum_b + 1e-6) ------------------------
__global__ void compute_z(const float* __restrict__ q, const float* __restrict__ ksum,
                          float* __restrict__ z)
{
    long long row = (long long)blockIdx.x * 8 + (threadIdx.x >> 5);
    int lane = threadIdx.x & 31;
    int b = (int)(row >> 12);
    const float* p  = q + row * CC;
    const float* ks = ksum + b * CC;
    float s = 0.f;
    for (int c = lane; c < CC; c += 32) s += p[c] * ks[c];
    #pragma unroll
    for (int o = 16; o > 0; o >>= 1) s += __shfl_xor_sync(0xffffffff, s, o);
    if (lane == 0) z[row] = 1.f / (s + 1e-6f);
}

// ---------------- LayerNorm over C=512 (tf32-rounded out) ------------------
__global__ void layernorm512(const float* __restrict__ in, float* __restrict__ out,
                             const float* __restrict__ g, const float* __restrict__ bta)
{
    long long row = blockIdx.x;
    const float* p = in + row * CC;
    int t = threadIdx.x; // 128
    float4 f4 = *reinterpret_cast<const float4*>(p + t * 4);
    float v[4] = { f4.x, f4.y, f4.z, f4.w };
    float s = v[0] + v[1] + v[2] + v[3];
    s = blockReduceSum(s);
    float mean = s * (1.f / (float)CC);
    float s2 = 0.f;
    #pragma unroll
    for (int r = 0; r < 4; r++) { float d = v[r] - mean; s2 += d * d; }
    s2 = blockReduceSum(s2);
    float rstd = rsqrtf(s2 * (1.f / (float)CC) + 1e-5f);
    float o[4];
    #pragma unroll
    for (int r = 0; r < 4; r++) {
        int c = t * 4 + r;
        o[r] = cvt_tf32((v[r] - mean) * rstd * g[c] + bta[c]);
    }
    *reinterpret_cast<float4*>(out + row * CC + t * 4) = make_float4(o[0], o[1], o[2], o[3]);
}

// ---------------- depthwise 3x3 + residual + LN(HID) + GELU (tf32 out) -----
__global__ void dw_ln_gelu(const float* __restrict__ a, const float* __restrict__ w,
                           const float* __restrict__ wb, const float* __restrict__ g,
                           const float* __restrict__ beta, float* __restrict__ out)
{
    long long idx = blockIdx.x;          // b*SS + s
    int b = (int)(idx >> 12);
    int s = (int)(idx & 4095);
    int y = s >> 6, x = s & 63;
    int t = threadIdx.x;                 // 256, each handles 8 channels
    const float* ab = a + (long long)b * SS * HD;

    float val[8];
    float sum = 0.f;
    #pragma unroll
    for (int r = 0; r < 8; r++) {
        int h = r * 256 + t;
        float acc = wb[h];
        #pragma unroll
        for (int ky = 0; ky < 3; ky++) {
            int yy = y + ky - 1;
            if (yy < 0 || yy > 63) continue;
            #pragma unroll
            for (int kx = 0; kx < 3; kx++) {
                int xx = x + kx - 1;
                if (xx < 0 || xx > 63) continue;
                acc += w[h * 9 + ky * 3 + kx] * ab[((long long)(yy * 64 + xx)) * HD + h];
            }
        }
        acc += ab[(long long)s * HD + h];      // + a (skip before LN)
        val[r] = acc;
        sum += acc;
    }
    sum = blockReduceSum(sum);
    float mean = sum * (1.f / (float)HD);
    float s2 = 0.f;
    #pragma unroll
    for (int r = 0; r < 8; r++) { float d = val[r] - mean; s2 += d * d; }
    s2 = blockReduceSum(s2);
    float rstd = rsqrtf(s2 * (1.f / (float)HD) + 1e-5f);
    #pragma unroll
    for (int r = 0; r < 8; r++) {
        int h = r * 256 + t;
        float yv = (val[r] - mean) * rstd * g[h] + beta[h];
        float ge = 0.5f * yv * (1.f + erff(yv * 0.70710678118654752f));
        out[idx * HD + h] = cvt_tf32(ge);
    }
}

// ---------------- launch ----------------------------------------------------
extern "C" void kernel_launch(void* const* d_in, const int* in_sizes, int n_in,
                              void* d_out, int out_size)
{
    const float* x      = (const float*)d_in[0];
    const float* Wq     = (const float*)d_in[1];
    const float* bq     = (const float*)d_in[2];
    const float* Wk     = (const float*)d_in[3];
    const float* bk     = (const float*)d_in[4];
    const float* Wv     = (const float*)d_in[5];
    const float* bv     = (const float*)d_in[6];
    const float* scale  = (const float*)d_in[7];
    const float* fc1_w  = (const float*)d_in[8];
    const float* fc1_b  = (const float*)d_in[9];
    const float* dw_w   = (const float*)d_in[10];
    const float* dw_b   = (const float*)d_in[11];
    const float* fc2_w  = (const float*)d_in[12];
    const float* fc2_b  = (const float*)d_in[13];
    const float* ln1_g  = (const float*)d_in[14];
    const float* ln1_b  = (const float*)d_in[15];
    const float* lnm_g  = (const float*)d_in[16];
    const float* lnm_b  = (const float*)d_in[17];
    float* out = (float*)d_out;

    void *pq, *pk, *pkt, *pv, *psc, *penh, *pt, *pa, *pax, *pkv, *pw1, *pw2, *pksum, *pz;
    cudaGetSymbolAddress(&pq,   g_q);
    cudaGetSymbolAddress(&pk,   g_k);
    cudaGetSymbolAddress(&pkt,  g_kt);
    cudaGetSymbolAddress(&pv,   g_v);
    cudaGetSymbolAddress(&psc,  g_sc);
    cudaGetSymbolAddress(&penh, g_enh);
    cudaGetSymbolAddress(&pt,   g_t);
    cudaGetSymbolAddress(&pa,   g_a);
    cudaGetSymbolAddress(&pax,  g_ax);
    cudaGetSymbolAddress(&pkv,  g_kv);
    cudaGetSymbolAddress(&pw1,  g_w1);
    cudaGetSymbolAddress(&pw2,  g_w2);
    cudaGetSymbolAddress(&pksum,g_ksum);
    cudaGetSymbolAddress(&pz,   g_z);

    // raise dynamic smem limits (host-side attribute set; not captured)
    cudaFuncSetAttribute(gemm_tc<0,true ,true ,false>, cudaFuncAttributeMaxDynamicSharedMemorySize, SMEM_GEMM_BYTES);
    cudaFuncSetAttribute(gemm_tc<0,false,true ,true >, cudaFuncAttributeMaxDynamicSharedMemorySize, SMEM_GEMM_BYTES);
    cudaFuncSetAttribute(gemm_tc<1,false,false,true >, cudaFuncAttributeMaxDynamicSharedMemorySize, SMEM_GEMM_BYTES);
    cudaFuncSetAttribute(gemm_tc<2,false,false,false>, cudaFuncAttributeMaxDynamicSharedMemorySize, SMEM_GEMM_BYTES);
    cudaFuncSetAttribute(gemm_tc<3,false,false,false>, cudaFuncAttributeMaxDynamicSharedMemorySize, SMEM_GEMM_BYTES);
    cudaFuncSetAttribute(gemm_tc<4,false,false,false>, cudaFuncAttributeMaxDynamicSharedMemorySize, SMEM_GEMM_BYTES);

    const long long BS  = (long long)CC * SS;
    const long long KVS = (long long)CC * CC;

    // 0. pre-round fc weights to tf32 (so fc GEMMs can skip cvt)
    round_tf32_kernel<<<(CC*HD/4 + 255)/256, 256>>>(fc1_w, (float*)pw1, CC*HD/4);
    round_tf32_kernel<<<(HD*CC/4 + 255)/256, 256>>>(fc2_w, (float*)pw2, HD*CC/4);

    // 1. shortcut = x^T per batch
    transpose_x<<<dim3(SS/32, CC/32, NB), dim3(32, 8)>>>(x, (float*)psc);

    // 2. qkv GEMMs: q,k split-tf32 (cvt in regs); v single-tf32 (cvt, rounded out)
    gemm_tc<0,true ,true ,false><<<dim3(SS/128, CC/128, NB), 256, SMEM_GEMM_BYTES>>>(
        Wq, x, (float*)pq, CC, SS, CC, 0, BS, BS, bq, nullptr, 0, 0);
    gemm_tc<0,true ,true ,false><<<dim3(SS/128, CC/128, NB), 256, SMEM_GEMM_BYTES>>>(
        Wk, x, (float*)pk, CC, SS, CC, 0, BS, BS, bk, nullptr, 0, 0);
    gemm_tc<0,false,true ,true ><<<dim3(SS/128, CC/128, NB), 256, SMEM_GEMM_BYTES>>>(
        Wv, x, (float*)pv, CC, SS, CC, 0, BS, BS, bv, nullptr, 0, 0);

    // 3. q path: column softmax, then row renorm^3 (tf32-rounded out)
    softmax_col_q<<<dim3(CC/32, NB), dim3(32, 16)>>>((float*)pq, scale);
    rownorm_pow3<<<NB*SS, 128>>>((float*)pq);

    // 4. k path: row softmax + transform + renorm + ksum (tf32-rounded out)
    zero_ksum<<<4, 1024>>>((float*)pksum);
    softmax_row_k<<<NB*SS, 128>>>((float*)pk, scale, (float*)pksum);

    // 4b. kT = transpose(k): (S,C) -> (C,S)
    transpose_sc<<<dim3(SS/32, CC/32, NB), dim3(32, 8)>>>((float*)pk, (float*)pkt);

    // 5. kv = kT @ v  (pre-rounded inputs -> no cvt; rounded out)
    gemm_tc<1,false,false,true ><<<dim3(CC/128, CC/128, NB), 256, SMEM_GEMM_BYTES>>>(
        (float*)pkt, (float*)pv, (float*)pkv, CC, CC, SS, BS, BS, KVS,
        nullptr, nullptr, 0, 0);

    // 6. z
    compute_z<<<NB*SS/8, 256>>>((float*)pq, (float*)pksum, (float*)pz);

    // 7. enhanced = shortcut + z * (q @ kv)  (pre-rounded inputs -> no cvt)
    gemm_tc<2,false,false,false><<<dim3(CC/128, SS/128, NB), 256, SMEM_GEMM_BYTES>>>(
        (float*)pq, (float*)pkv, (float*)penh, SS, CC, CC, BS, KVS, BS,
        (float*)pz, (float*)psc, SS, BS);

    // 8. t = LN(enhanced) (tf32-rounded out)
    layernorm512<<<NB*SS, 128>>>((float*)penh, (float*)pt, lnm_g, lnm_b);

    // 9. a = t @ w1 + fc1_b  (pre-rounded inputs -> no cvt)
    gemm_tc<3,false,false,false><<<dim3(HD/128, (NB*SS)/128, 1), 256, SMEM_GEMM_BYTES>>>(
        (float*)pt, (float*)pw1, (float*)pa, NB*SS, HD, CC, 0, 0, 0,
        fc1_b, nullptr, 0, 0);

    // 10. ax = gelu(LN(dwconv3x3(a) + dw_b + a)) (tf32-rounded out)
    dw_ln_gelu<<<NB*SS, 256>>>((float*)pa, dw_w, dw_b, ln1_g, ln1_b, (float*)pax);

    // 11. out = enhanced + ax @ w2 + fc2_b  (pre-rounded inputs -> no cvt)
    gemm_tc<4,false,false,false><<<dim3(CC/128, (NB*SS)/128, 1), 256, SMEM_GEMM_BYTES>>>(
        (float*)pax, (float*)pw2, out, NB*SS, CC, HD, 0, 0, 0,
        fc2_b, (float*)penh, 0, 0);
}